// round 4
// baseline (speedup 1.0000x reference)
#include <cuda_runtime.h>

// ---------------------------------------------------------------------------
// TimemixingFC_channel, round 4: f32x2 packed-FMA GEMM phases (2x fp32 rate).
//   Branch algebra unchanged from R3: qkv -> 2x2 G per group -> o -> proj,
//   branch-0 proj folded into branch-1 QKV (W' = Wsw@Wp, b' = Wsw@bp + bsw).
//   GEMM tiles: 16x16 thread grid, 7 rows x 3 col-pairs, fma.rn.f32x2.
//   A operand duplicated in smem (xs2[l][2c]=[2c+1]) so both operands are
//   natural LDS.64; accumulator pairs land in kb/vb via STS.64.
// ---------------------------------------------------------------------------

typedef unsigned long long u64;

#define SMEM_FLOATS 54736
#define SMEM_BYTES  (SMEM_FLOATS * 4)

__device__ float g_mid[2 * 16 * 32 * 32 * 96];   // o0 intermediate (pre-proj)
__device__ float g_wT [2][3 * 96 * 96];          // [branch][comp][c][j]; branch1 = W'
__device__ float g_wTp[96 * 96];                 // branch-1 FINAL proj (projs_w), [c][j]
__device__ float g_b1 [3 * 96];                  // b' = Wsw@bp + bsw

__device__ __forceinline__ u64 ffma2(u64 a, u64 b, u64 c) {
    u64 d;
    asm("fma.rn.f32x2 %0, %1, %2, %3;" : "=l"(d) : "l"(a), "l"(b), "l"(c));
    return d;
}

// ---------------------------------------------------------------------------
// Prep A: pure transposes. Grid 144 x 256.
//   blocks [0,108):   transpose lr_w    -> g_wT[0]
//   blocks [108,144): transpose projs_w -> g_wTp
// ---------------------------------------------------------------------------
__global__ void prep_transpose(const float* __restrict__ lr,
                               const float* __restrict__ prs)
{
    int bid = blockIdx.x, tid = threadIdx.x;
    if (bid < 108) {
        int idx = bid * 256 + tid;            // < 27648
        int jf = idx / 96, c = idx % 96;
        g_wT[0][(jf / 96) * 9216 + c * 96 + (jf % 96)] = lr[idx];
    } else {
        int idx = (bid - 108) * 256 + tid;    // < 9216
        int j = idx / 96, c = idx % 96;
        g_wTp[c * 96 + j] = prs[idx];
    }
}

// ---------------------------------------------------------------------------
// Prep B: fold W' = sw @ pr (+ b'). Grid 25 x 96.
//   blocks [0,24): 12 rows of W' each, register-tiled (12 acc per thread).
//   block 24:      b' = sw @ prb + swb.
// ---------------------------------------------------------------------------
__global__ void prep_fold(const float* __restrict__ pr,
                          const float* __restrict__ sw,
                          const float* __restrict__ swb,
                          const float* __restrict__ prb)
{
    int bid = blockIdx.x, tid = threadIdx.x;
    if (bid < 24) {
        __shared__ float sws[12 * 96];
        int jf0 = bid * 12;
        for (int i = tid; i < 1152; i += 96) sws[i] = sw[jf0 * 96 + i];
        __syncthreads();
        int c = tid;
        float acc[12];
#pragma unroll
        for (int r = 0; r < 12; r++) acc[r] = 0.f;
#pragma unroll 4
        for (int t = 0; t < 96; t++) {
            float p = __ldg(&pr[t * 96 + c]);
#pragma unroll
            for (int r = 0; r < 12; r++)
                acc[r] = fmaf(sws[r * 96 + t], p, acc[r]);
        }
#pragma unroll
        for (int r = 0; r < 12; r++) {
            int jf = jf0 + r;
            g_wT[1][(jf / 96) * 9216 + c * 96 + (jf % 96)] = acc[r];
        }
    } else {
        for (int r = tid; r < 288; r += 96) {
            const float* swr = sw + r * 96;
            float s = swb[r];
#pragma unroll 8
            for (int t = 0; t < 96; t++) s = fmaf(swr[t], prb[t], s);
            g_b1[r] = s;
        }
    }
}

// ---------------------------------------------------------------------------
// f32x2 register-tiled sub-GEMM: 256 thr = 16 rgrp (7 rows) x 16 cgrp (3 col
// pairs). A duplicated in smem (stride 196, LDS.64 -> {a,a}); B natural pairs
// from ws (stride 100, LDS.64). 21 FFMA2 per k-step per thread.
// ---------------------------------------------------------------------------
__device__ __forceinline__ void gemm_tile2(const float* __restrict__ As2,
                                           const float* __restrict__ Ws,
                                           const float* __restrict__ bias,
                                           int r0, int j0, u64 acc[7][3])
{
    u64 binit[3];
#pragma unroll
    for (int jp = 0; jp < 3; jp++)
        binit[jp] = *(const u64*)&bias[j0 + 2 * jp];
#pragma unroll
    for (int rr = 0; rr < 7; rr++)
#pragma unroll
        for (int jp = 0; jp < 3; jp++) acc[rr][jp] = binit[jp];

    const float* a0 = As2 + r0 * 196;
#pragma unroll 4
    for (int c = 0; c < 96; c++) {
        u64 a[7];
#pragma unroll
        for (int rr = 0; rr < 7; rr++)
            a[rr] = *(const u64*)&a0[rr * 196 + 2 * c];
        u64 b[3];
        const float* wr = Ws + c * 100 + j0;
#pragma unroll
        for (int jp = 0; jp < 3; jp++)
            b[jp] = *(const u64*)&wr[2 * jp];
#pragma unroll
        for (int rr = 0; rr < 7; rr++)
#pragma unroll
            for (int jp = 0; jp < 3; jp++)
                acc[rr][jp] = ffma2(a[rr], b[jp], acc[rr][jp]);
    }
}

// ---------------------------------------------------------------------------
// Fused branch kernel. Grid = 296 (2 exact waves). Block: P (55/56) position
// groups = 2P tokens. Phases: stage x (dup) -> K -> V -> G -> Q -> o (-> proj).
// ---------------------------------------------------------------------------
__global__ void __launch_bounds__(256)
fused_branch(const float* __restrict__ xin_ext,
             const float* __restrict__ qkv_b_ext,
             const float* __restrict__ pr_b,
             float* __restrict__ out_ext,
             int branch, int shift)
{
    extern __shared__ float sm[];
    float* xs2 = sm;             // 112 x 196 (x duplicated; later o dup, branch1)
    float* ws  = sm + 21952;     // 96 x 100
    float* kb  = sm + 31552;     // 112 x 100 (k, then q)
    float* vb  = sm + 42752;     // 112 x 100 (v)
    float* gt  = sm + 53952;     // 112 x 4
    float* gc  = sm + 54400;     // 56 x 4
    int*   tb  = (int*)(sm + 54624); // 112 token gmem bases

    const float* X  = branch ? g_mid : xin_ext;
    float*       O  = branch ? out_ext : g_mid;
    const float* WQ = g_wT[branch];
    const float* QB = branch ? g_b1 : qkv_b_ext;

    int tid = threadIdx.x, bid = blockIdx.x;
    int P, s;
    if (bid < 104) { P = 56; s = bid * 56; }
    else           { P = 55; s = 5824 + (bid - 104) * 55; }
    int T = 2 * P, F4 = T * 24;

    if (tid < T) {
        int pi = tid < P ? tid : tid - P;
        int g = s + pi;
        int b = g >> 13, dw = (g >> 10) & 7, p = g & 1023;
        int d = (2 * dw + (tid < P ? 0 : 1) + shift) & 15;
        tb[tid] = ((b * 16 + d) * 1024 + p) * 96;
    }
    __syncthreads();

    // stage x duplicated: xs2[l][2c] = xs2[l][2c+1] = x[l][c]
    for (int f4 = tid; f4 < 2688; f4 += 256) {
        int l = f4 / 24, q4 = f4 % 24;
        float4 v = make_float4(0.f, 0.f, 0.f, 0.f);
        if (l < T) v = *(const float4*)&X[tb[l] + q4 * 4];
        float* dst = &xs2[l * 196 + q4 * 8];
        *(float4*)(dst)     = make_float4(v.x, v.x, v.y, v.y);
        *(float4*)(dst + 4) = make_float4(v.z, v.z, v.w, v.w);
    }

    int cgrp = tid & 15, rgrp = tid >> 4;
    int r0 = rgrp * 7, j0 = cgrp * 6;
    u64 acc[7][3];

    // ---- K ----
    for (int f4 = tid; f4 < 2304; f4 += 256) {
        int c = f4 / 24, q = (f4 % 24) * 4;
        *(float4*)&ws[c * 100 + q] = *(const float4*)&WQ[9216 + c * 96 + q];
    }
    __syncthreads();
    gemm_tile2(xs2, ws, QB + 96, r0, j0, acc);
#pragma unroll
    for (int rr = 0; rr < 7; rr++)
#pragma unroll
        for (int jp = 0; jp < 3; jp++)
            *(u64*)&kb[(r0 + rr) * 100 + j0 + 2 * jp] = acc[rr][jp];
    __syncthreads();

    // ---- V ----
    for (int f4 = tid; f4 < 2304; f4 += 256) {
        int c = f4 / 24, q = (f4 % 24) * 4;
        *(float4*)&ws[c * 100 + q] = *(const float4*)&WQ[2 * 9216 + c * 96 + q];
    }
    __syncthreads();
    gemm_tile2(xs2, ws, QB + 192, r0, j0, acc);
#pragma unroll
    for (int rr = 0; rr < 7; rr++)
#pragma unroll
        for (int jp = 0; jp < 3; jp++)
            *(u64*)&vb[(r0 + rr) * 100 + j0 + 2 * jp] = acc[rr][jp];
    __syncthreads();

    // ---- stage Q weights + per-group 2x2 G ----
    for (int f4 = tid; f4 < 2304; f4 += 256) {
        int c = f4 / 24, q = (f4 % 24) * 4;
        *(float4*)&ws[c * 100 + q] = *(const float4*)&WQ[c * 96 + q];
    }
    {
        int l = tid >> 1, h = tid & 1;
        float g00 = 0, g01 = 0, g10 = 0, g11 = 0;
        if (l < T) {
            const float4* k4p = (const float4*)kb;   // row stride 25 f4
            const float4* v4p = (const float4*)vb;
            int base = l * 25 + h * 12;
#pragma unroll
            for (int ss = 0; ss < 12; ss++) {
                float4 k4 = k4p[base + ss];
                float4 v4 = v4p[base + ss];
                g00 = fmaf(k4.x, v4.x, fmaf(k4.z, v4.z, g00));
                g01 = fmaf(k4.x, v4.y, fmaf(k4.z, v4.w, g01));
                g10 = fmaf(k4.y, v4.x, fmaf(k4.w, v4.z, g10));
                g11 = fmaf(k4.y, v4.y, fmaf(k4.w, v4.w, g11));
            }
            if (h == 1) {
                gt[l * 4] = g00; gt[l * 4 + 1] = g01;
                gt[l * 4 + 2] = g10; gt[l * 4 + 3] = g11;
            }
        }
        __syncthreads();
        if (l < T && h == 0) {
            gt[l * 4]     += g00; gt[l * 4 + 1] += g01;
            gt[l * 4 + 2] += g10; gt[l * 4 + 3] += g11;
        }
        __syncthreads();
        if (tid < P) {
#pragma unroll
            for (int k = 0; k < 4; k++)
                gc[tid * 4 + k] = gt[tid * 4 + k] + gt[(tid + P) * 4 + k];
        }
    }
    __syncthreads();

    // ---- Q -> kb ----
    gemm_tile2(xs2, ws, QB, r0, j0, acc);
#pragma unroll
    for (int rr = 0; rr < 7; rr++)
#pragma unroll
        for (int jp = 0; jp < 3; jp++)
            *(u64*)&kb[(r0 + rr) * 100 + j0 + 2 * jp] = acc[rr][jp];
    __syncthreads();

    if (branch == 0) {
        // ---- o = q @ G, streamed straight to gmem (g_mid) ----
        const float4* k4p = (const float4*)kb;
        for (int f4 = tid; f4 < F4; f4 += 256) {
            int l = f4 / 24, sf = f4 % 24;
            int pi = l < P ? l : l - P;
            float G00 = gc[pi * 4], G01 = gc[pi * 4 + 1];
            float G10 = gc[pi * 4 + 2], G11 = gc[pi * 4 + 3];
            float4 q4 = k4p[l * 25 + sf];
            float4 o4;
            o4.x = q4.x * G00 + q4.y * G10;
            o4.y = q4.x * G01 + q4.y * G11;
            o4.z = q4.z * G00 + q4.w * G10;
            o4.w = q4.z * G01 + q4.w * G11;
            *(float4*)&O[tb[l] + sf * 4] = o4;
        }
    } else {
        // ---- stage FINAL proj weights + o = q @ G -> xs2 (duplicated) ----
        for (int f4 = tid; f4 < 2304; f4 += 256) {
            int c = f4 / 24, q = (f4 % 24) * 4;
            *(float4*)&ws[c * 100 + q] = *(const float4*)&g_wTp[c * 96 + q];
        }
        {
            const float4* k4p = (const float4*)kb;
            for (int f4 = tid; f4 < F4; f4 += 256) {
                int l = f4 / 24, sf = f4 % 24;
                int pi = l < P ? l : l - P;
                float G00 = gc[pi * 4], G01 = gc[pi * 4 + 1];
                float G10 = gc[pi * 4 + 2], G11 = gc[pi * 4 + 3];
                float4 q4 = k4p[l * 25 + sf];
                float4 o4;
                o4.x = q4.x * G00 + q4.y * G10;
                o4.y = q4.x * G01 + q4.y * G11;
                o4.z = q4.z * G00 + q4.w * G10;
                o4.w = q4.z * G01 + q4.w * G11;
                float* dst = &xs2[l * 196 + sf * 8];
                *(float4*)(dst)     = make_float4(o4.x, o4.x, o4.y, o4.y);
                *(float4*)(dst + 4) = make_float4(o4.z, o4.z, o4.w, o4.w);
            }
        }
        __syncthreads();

        // ---- proj GEMM -> out ----
        gemm_tile2(xs2, ws, pr_b, r0, j0, acc);
#pragma unroll
        for (int rr = 0; rr < 7; rr++) {
            int l = r0 + rr;
            if (l < T) {
                int g = tb[l] + j0;
#pragma unroll
                for (int jp = 0; jp < 3; jp++)
                    *(u64*)&O[g + 2 * jp] = acc[rr][jp];
            }
        }
    }
}

// ---------------------------------------------------------------------------
extern "C" void kernel_launch(void* const* d_in, const int* in_sizes, int n_in,
                              void* d_out, int out_size)
{
    const float* x       = (const float*)d_in[0];
    const float* lr_w    = (const float*)d_in[1];
    const float* lr_b    = (const float*)d_in[2];
    const float* proj_w  = (const float*)d_in[3];
    const float* proj_b  = (const float*)d_in[4];
    const float* sw_w    = (const float*)d_in[5];
    const float* sw_b    = (const float*)d_in[6];
    const float* projs_w = (const float*)d_in[7];
    const float* projs_b = (const float*)d_in[8];
    float* out = (float*)d_out;

    cudaFuncSetAttribute(fused_branch,
                         cudaFuncAttributeMaxDynamicSharedMemorySize, SMEM_BYTES);

    prep_transpose<<<144, 256>>>(lr_w, projs_w);
    prep_fold<<<25, 96>>>(proj_w, sw_w, sw_b, proj_b);
    // branch 0: pairs (2w, 2w+1), x -> o0 (g_mid); proj folded forward
    fused_branch<<<296, 256, SMEM_BYTES>>>(x, lr_b, nullptr, nullptr, 0, 0);
    // branch 1: pairs ((2w+15)&15, 2w); qkv' on o0, projs -> out
    fused_branch<<<296, 256, SMEM_BYTES>>>(nullptr, nullptr, projs_b, out, 1, 15);
}

// round 6
// speedup vs baseline: 3.4621x; 3.4621x over previous
#include <cuda_runtime.h>
#include <cuda_bf16.h>
#include <cstdint>

// ---------------------------------------------------------------------------
// TimemixingFC_channel, round 6: mma.sync (m16n8k16 bf16, fp32 accum) for all
// GEMM phases — tcgen05 is unavailable under the harness's compute_100 PTX
// target, but Ampere-era mma.sync lowers to Blackwell fallback HMMA.
//   Algebra as R3: per branch qkv = x@W^T + b; S=2 attention -> 2x2 G per
//   (position, window) group; o = q@G; proj. Branch-0 proj folded into
//   branch-1 qkv (W' = Wsw@Wp, b' = Wsw@bp + bsw). Rolls folded into pairing.
//   D-fragment pairs (j0, j0+1) = one S=2 segment -> G computed directly from
//   k/v accumulator registers + shfl reduce. No k/v smem buffers.
// Grid 256 x 256thr (8 warps, warp = 16 D-rows); 51.7KB smem, 2 blocks/SM ->
// single wave.
// ---------------------------------------------------------------------------

#define SMEM_BYTES 51712

static __device__ __align__(16) __nv_bfloat16 g_mid[32768 * 96];   // o0 (bf16)
static __device__ __align__(16) __nv_bfloat16 g_wbf[2][288 * 104]; // qkv W, [jf][c] pad104
static __device__ __align__(16) __nv_bfloat16 g_wpbf[96 * 104];    // projs_w
static __device__ float g_b1[288];                                 // b' fold bias

// ---------------------------------------------------------------------------
// Prep A: bf16-convert lr_w and projs_w into padded [j][c] images. 144 x 256.
// ---------------------------------------------------------------------------
__global__ void prep_w(const float* __restrict__ lr,
                       const float* __restrict__ prs)
{
    int idx = blockIdx.x * 256 + threadIdx.x;   // < 36864
    if (idx < 27648) {
        int jf = idx / 96, c = idx % 96;
        g_wbf[0][jf * 104 + c] = __float2bfloat16(lr[idx]);
    } else {
        idx -= 27648;
        int j = idx / 96, c = idx % 96;
        g_wpbf[j * 104 + c] = __float2bfloat16(prs[idx]);
    }
}

// ---------------------------------------------------------------------------
// Prep B: W' = sw_w @ proj_w (fp32, bf16 store) ; b' = sw_w @ proj_b + sw_b.
// Grid 25 x 96.
// ---------------------------------------------------------------------------
__global__ void prep_fold(const float* __restrict__ pr,
                          const float* __restrict__ sw,
                          const float* __restrict__ swb,
                          const float* __restrict__ prb)
{
    int bid = blockIdx.x, tid = threadIdx.x;
    if (bid < 24) {
        __shared__ float sws[12 * 96];
        int jf0 = bid * 12;
        for (int i = tid; i < 1152; i += 96) sws[i] = sw[jf0 * 96 + i];
        __syncthreads();
        int c = tid;
        float acc[12];
#pragma unroll
        for (int r = 0; r < 12; r++) acc[r] = 0.f;
#pragma unroll 4
        for (int t = 0; t < 96; t++) {
            float p = __ldg(&pr[t * 96 + c]);
#pragma unroll
            for (int r = 0; r < 12; r++) acc[r] = fmaf(sws[r * 96 + t], p, acc[r]);
        }
#pragma unroll
        for (int r = 0; r < 12; r++)
            g_wbf[1][(jf0 + r) * 104 + c] = __float2bfloat16(acc[r]);
    } else {
        for (int r = tid; r < 288; r += 96) {
            const float* swr = sw + r * 96;
            float s = swb[r];
#pragma unroll 8
            for (int t = 0; t < 96; t++) s = fmaf(swr[t], prb[t], s);
            g_b1[r] = s;
        }
    }
}

// ---------------------------------------------------------------------------
// One GEMM phase: warp computes D[16 x 96] = A[16 x 96] @ B[96 x 96]^T.
// A: smA [128][104] bf16 row-major; B: smW [96][104] bf16 ([n][k]).
// 12 n-tiles x 6 k-steps of m16n8k16. All fragment loads are LDS.32,
// conflict-free (row stride 104 bf16 -> bank starts step by 4).
// ---------------------------------------------------------------------------
__device__ __forceinline__ void hmma_phase(const char* smA_, const char* smW_,
                                           int row0, int g, int tig,
                                           float acc[12][4])
{
#pragma unroll
    for (int nt = 0; nt < 12; nt++)
#pragma unroll
        for (int r = 0; r < 4; r++) acc[nt][r] = 0.f;
#pragma unroll
    for (int ks = 0; ks < 6; ks++) {
        uint32_t a0 = *(const uint32_t*)(smA_ + ((row0 + g)     * 104 + ks * 16 +     tig * 2) * 2);
        uint32_t a1 = *(const uint32_t*)(smA_ + ((row0 + g + 8) * 104 + ks * 16 +     tig * 2) * 2);
        uint32_t a2 = *(const uint32_t*)(smA_ + ((row0 + g)     * 104 + ks * 16 + 8 + tig * 2) * 2);
        uint32_t a3 = *(const uint32_t*)(smA_ + ((row0 + g + 8) * 104 + ks * 16 + 8 + tig * 2) * 2);
#pragma unroll
        for (int nt = 0; nt < 12; nt++) {
            uint32_t b0 = *(const uint32_t*)(smW_ + ((nt * 8 + g) * 104 + ks * 16 +     tig * 2) * 2);
            uint32_t b1 = *(const uint32_t*)(smW_ + ((nt * 8 + g) * 104 + ks * 16 + 8 + tig * 2) * 2);
            asm volatile(
                "mma.sync.aligned.m16n8k16.row.col.f32.bf16.bf16.f32 "
                "{%0,%1,%2,%3}, {%4,%5,%6,%7}, {%8,%9}, {%0,%1,%2,%3};"
                : "+f"(acc[nt][0]), "+f"(acc[nt][1]), "+f"(acc[nt][2]), "+f"(acc[nt][3])
                : "r"(a0), "r"(a1), "r"(a2), "r"(a3), "r"(b0), "r"(b1));
        }
    }
}

__device__ __forceinline__ void add_bias(const float* __restrict__ bias,
                                         int tig, float acc[12][4])
{
#pragma unroll
    for (int nt = 0; nt < 12; nt++) {
        float b0 = bias[nt * 8 + tig * 2], b1 = bias[nt * 8 + tig * 2 + 1];
        acc[nt][0] += b0; acc[nt][1] += b1; acc[nt][2] += b0; acc[nt][3] += b1;
    }
}

__device__ __forceinline__ void stage_w(char* smW, const char* src, int tid)
{
    uint4* dst = (uint4*)smW;
    const uint4* s = (const uint4*)src;
    for (int f = tid; f < 1248; f += 256) dst[f] = s[f];   // 96*208 bytes
}

// ---------------------------------------------------------------------------
// Fused branch. Grid 256 x 256. Block = 64 position-groups x 2 frames.
// ---------------------------------------------------------------------------
__global__ void __launch_bounds__(256, 2)
fused_branch(const float* __restrict__ xin_ext,
             const float* __restrict__ qkv_b_ext,
             const float* __restrict__ pr_b,
             float* __restrict__ out_ext,
             int branch, int shift)
{
    extern __shared__ char smem[];
    int*   tb = (int*)smem;                 // 128 token bases
    float* qb = (float*)(smem + 512);       // 288 qkv biases
    float* pb = (float*)(smem + 1664);      // 96 proj biases
    float* gt = (float*)(smem + 2048);      // 128 x 4 per-token G
    float* gc = (float*)(smem + 4096);      // 64 x 4 per-group G
    char*  smA = smem + 5120;               // [128][104] bf16 (x / o tile)
    char*  smW = smem + 31744;              // [96][104] bf16 weight slot

    int tid = threadIdx.x, w = tid >> 5, lane = tid & 31;
    int g = lane >> 2, tig = lane & 3;
    int row0 = w * 16;

    const float* QB = branch ? g_b1 : qkv_b_ext;
    for (int i = tid; i < 288; i += 256) qb[i] = QB[i];
    if (branch && tid < 96) pb[tid] = pr_b[tid];

    if (tid < 128) {
        int pi = tid & 63;
        int gg = (blockIdx.x << 6) + pi;
        int b = gg >> 13, dw = (gg >> 10) & 7, p = gg & 1023;
        int d = (2 * dw + (tid >> 6) + shift) & 15;
        tb[tid] = ((b * 16 + d) * 1024 + p) * 96;
    }
    __syncthreads();

    // ---- stage A tile (bf16 [128][104]) + K weights ----
    if (branch == 0) {
        for (int f4 = tid; f4 < 3072; f4 += 256) {
            int l = f4 / 24, q4 = f4 % 24;
            float4 v = *(const float4*)&xin_ext[tb[l] + q4 * 4];
            __nv_bfloat162 p0 = __floats2bfloat162_rn(v.x, v.y);
            __nv_bfloat162 p1 = __floats2bfloat162_rn(v.z, v.w);
            *(uint2*)(smA + l * 208 + q4 * 8) =
                make_uint2(*(uint32_t*)&p0, *(uint32_t*)&p1);
        }
    } else {
        for (int f = tid; f < 1536; f += 256) {
            int l = f / 12, u = f % 12;
            *(uint4*)(smA + l * 208 + u * 16) =
                *(const uint4*)((const char*)g_mid + (size_t)tb[l] * 2 + u * 16);
        }
    }
    const char* WB = (const char*)g_wbf[branch];
    stage_w(smW, WB + 96 * 208, tid);          // K weights
    __syncthreads();

    float kacc[12][4], vacc[12][4];

    // ---- K ----
    hmma_phase(smA, smW, row0, g, tig, kacc);
    add_bias(qb + 96, tig, kacc);
    __syncthreads();

    // ---- V ----
    stage_w(smW, WB + 192 * 208, tid);
    __syncthreads();
    hmma_phase(smA, smW, row0, g, tig, vacc);
    add_bias(qb + 192, tig, vacc);

    // ---- per-token 2x2 G from k/v accumulator registers ----
    {
        float G[8];   // rows g (0..3) and g+8 (4..7): {00,01,10,11}
#pragma unroll
        for (int i = 0; i < 8; i++) G[i] = 0.f;
#pragma unroll
        for (int nt = 0; nt < 12; nt++) {
            G[0] = fmaf(kacc[nt][0], vacc[nt][0], G[0]);
            G[1] = fmaf(kacc[nt][0], vacc[nt][1], G[1]);
            G[2] = fmaf(kacc[nt][1], vacc[nt][0], G[2]);
            G[3] = fmaf(kacc[nt][1], vacc[nt][1], G[3]);
            G[4] = fmaf(kacc[nt][2], vacc[nt][2], G[4]);
            G[5] = fmaf(kacc[nt][2], vacc[nt][3], G[5]);
            G[6] = fmaf(kacc[nt][3], vacc[nt][2], G[6]);
            G[7] = fmaf(kacc[nt][3], vacc[nt][3], G[7]);
        }
#pragma unroll
        for (int off = 1; off <= 2; off <<= 1)
#pragma unroll
            for (int i = 0; i < 8; i++)
                G[i] += __shfl_xor_sync(0xffffffffu, G[i], off);
        __syncthreads();                       // all warps done reading smW_V
        if (tig == 0) {
            *(float4*)&gt[(row0 + g) * 4]     = make_float4(G[0], G[1], G[2], G[3]);
            *(float4*)&gt[(row0 + g + 8) * 4] = make_float4(G[4], G[5], G[6], G[7]);
        }
        stage_w(smW, WB, tid);                 // Q weights (overlap with gt)
    }
    __syncthreads();
    if (tid < 64) {
        float4 a = *(float4*)&gt[tid * 4];
        float4 b4 = *(float4*)&gt[(tid + 64) * 4];
        *(float4*)&gc[tid * 4] =
            make_float4(a.x + b4.x, a.y + b4.y, a.z + b4.z, a.w + b4.w);
    }
    __syncthreads();

    // ---- Q (reuse kacc) + o = q @ G, written (bf16) into own smA rows ----
    hmma_phase(smA, smW, row0, g, tig, kacc);
    add_bias(qb, tig, kacc);
    {
        float4 Glo = *(float4*)&gc[((row0 + g) & 63) * 4];
        float4 Ghi = *(float4*)&gc[((row0 + g + 8) & 63) * 4];
#pragma unroll
        for (int nt = 0; nt < 12; nt++) {
            int j0 = nt * 8 + tig * 2;
            float o0 = kacc[nt][0] * Glo.x + kacc[nt][1] * Glo.z;
            float o1 = kacc[nt][0] * Glo.y + kacc[nt][1] * Glo.w;
            float o2 = kacc[nt][2] * Ghi.x + kacc[nt][3] * Ghi.z;
            float o3 = kacc[nt][2] * Ghi.y + kacc[nt][3] * Ghi.w;
            __nv_bfloat162 plo = __floats2bfloat162_rn(o0, o1);
            __nv_bfloat162 phi = __floats2bfloat162_rn(o2, o3);
            *(uint32_t*)(smA + (row0 + g) * 208 + j0 * 2)     = *(uint32_t*)&plo;
            *(uint32_t*)(smA + (row0 + g + 8) * 208 + j0 * 2) = *(uint32_t*)&phi;
        }
    }

    if (branch == 0) {
        // ---- o tile -> g_mid (coalesced uint4 rows) ----
        __syncthreads();
        for (int f = tid; f < 1536; f += 256) {
            int l = f / 12, u = f % 12;
            *(uint4*)((char*)g_mid + (size_t)tb[l] * 2 + u * 16) =
                *(const uint4*)(smA + l * 208 + u * 16);
        }
    } else {
        // ---- proj: o tile @ projs_w^T + pb -> out ----
        __syncthreads();
        stage_w(smW, (const char*)g_wpbf, tid);
        __syncthreads();
        hmma_phase(smA, smW, row0, g, tig, kacc);
        int tbg = tb[row0 + g], tbh = tb[row0 + g + 8];
#pragma unroll
        for (int nt = 0; nt < 12; nt++) {
            int j0 = nt * 8 + tig * 2;
            float b0 = pb[j0], b1 = pb[j0 + 1];
            *(float2*)&out_ext[tbg + j0] =
                make_float2(kacc[nt][0] + b0, kacc[nt][1] + b1);
            *(float2*)&out_ext[tbh + j0] =
                make_float2(kacc[nt][2] + b0, kacc[nt][3] + b1);
        }
    }
}

// ---------------------------------------------------------------------------
extern "C" void kernel_launch(void* const* d_in, const int* in_sizes, int n_in,
                              void* d_out, int out_size)
{
    const float* x       = (const float*)d_in[0];
    const float* lr_w    = (const float*)d_in[1];
    const float* lr_b    = (const float*)d_in[2];
    const float* proj_w  = (const float*)d_in[3];
    const float* proj_b  = (const float*)d_in[4];
    const float* sw_w    = (const float*)d_in[5];
    const float* sw_b    = (const float*)d_in[6];
    const float* projs_w = (const float*)d_in[7];
    const float* projs_b = (const float*)d_in[8];
    float* out = (float*)d_out;

    cudaFuncSetAttribute(fused_branch,
                         cudaFuncAttributeMaxDynamicSharedMemorySize, SMEM_BYTES);

    prep_w<<<144, 256>>>(lr_w, projs_w);
    prep_fold<<<25, 96>>>(proj_w, sw_w, sw_b, proj_b);
    // branch 0: pairs (2w, 2w+1), x -> o0 (g_mid bf16); proj folded forward
    fused_branch<<<256, 256, SMEM_BYTES>>>(x, lr_b, nullptr, nullptr, 0, 0);
    // branch 1: pairs ((2w+15)&15, 2w); qkv' on o0, projs -> out
    fused_branch<<<256, 256, SMEM_BYTES>>>(nullptr, nullptr, projs_b, out, 1, 15);
}

// round 7
// speedup vs baseline: 3.8178x; 1.1027x over previous
#include <cuda_runtime.h>
#include <cuda_bf16.h>
#include <cstdint>

// ---------------------------------------------------------------------------
// TimemixingFC_channel, round 7: mma.sync + ldmatrix.x4 + cp.async pipelining.
//   Algebra as before: per branch qkv = x@W^T + b; S=2 attention -> 2x2 G per
//   (position, window) group; o = q@G; proj. Branch-0 proj folded into
//   branch-1 qkv (W' = Wsw@Wp, b' = Wsw@bp + bsw). Rolls folded into pairing.
//   R7 changes vs R6 (which was latency-bound: issue 17.8%, tensor 17.4%):
//     - ldmatrix.x4 fragment loads (168 LDS -> 42 LDSM per phase)
//     - cp.async triple-buffered weight staging (K/V/Q [+proj]) overlapping
//       compute; A tile via cp.async for branch 1
// Grid 256 x 256thr, 2 blocks/SM, 1 wave. smem 89.5KB/block.
// ---------------------------------------------------------------------------

#define SMEM_BYTES 91648

static __device__ __align__(16) __nv_bfloat16 g_mid[32768 * 96];   // o0 (bf16)
static __device__ __align__(16) __nv_bfloat16 g_wbf[2][288 * 104]; // qkv W, [jf][c] pad104
static __device__ __align__(16) __nv_bfloat16 g_wpbf[96 * 104];    // projs_w
static __device__ float g_b1[288];                                 // b' fold bias

// ---- PTX helpers (all valid under compute_100) ----------------------------
__device__ __forceinline__ uint32_t smem_u32(const void* p) {
    uint32_t a;
    asm("{ .reg .u64 t; cvta.to.shared.u64 t, %1; cvt.u32.u64 %0, t; }" : "=r"(a) : "l"(p));
    return a;
}
#define CPA16(dst, src) \
    asm volatile("cp.async.cg.shared.global [%0], [%1], 16;" :: "r"(dst), "l"(src) : "memory")
#define CPA_COMMIT() asm volatile("cp.async.commit_group;" ::: "memory")
#define CPA_WAIT(n)  asm volatile("cp.async.wait_group %0;" :: "n"(n) : "memory")

__device__ __forceinline__ void ldsm4(uint32_t& r0, uint32_t& r1, uint32_t& r2,
                                      uint32_t& r3, uint32_t addr) {
    asm volatile("ldmatrix.sync.aligned.m8n8.x4.shared.b16 {%0,%1,%2,%3}, [%4];"
                 : "=r"(r0), "=r"(r1), "=r"(r2), "=r"(r3) : "r"(addr));
}

// ---------------------------------------------------------------------------
// Prep A: bf16-convert lr_w and projs_w into padded [j][c] images. 144 x 256.
// ---------------------------------------------------------------------------
__global__ void prep_w(const float* __restrict__ lr,
                       const float* __restrict__ prs)
{
    int idx = blockIdx.x * 256 + threadIdx.x;   // < 36864
    if (idx < 27648) {
        int jf = idx / 96, c = idx % 96;
        g_wbf[0][jf * 104 + c] = __float2bfloat16(lr[idx]);
    } else {
        idx -= 27648;
        int j = idx / 96, c = idx % 96;
        g_wpbf[j * 104 + c] = __float2bfloat16(prs[idx]);
    }
}

// ---------------------------------------------------------------------------
// Prep B: W' = sw_w @ proj_w (fp32, bf16 store) ; b' = sw_w @ proj_b + sw_b.
// Grid 25 x 96.
// ---------------------------------------------------------------------------
__global__ void prep_fold(const float* __restrict__ pr,
                          const float* __restrict__ sw,
                          const float* __restrict__ swb,
                          const float* __restrict__ prb)
{
    int bid = blockIdx.x, tid = threadIdx.x;
    if (bid < 24) {
        __shared__ float sws[12 * 96];
        int jf0 = bid * 12;
        for (int i = tid; i < 1152; i += 96) sws[i] = sw[jf0 * 96 + i];
        __syncthreads();
        int c = tid;
        float acc[12];
#pragma unroll
        for (int r = 0; r < 12; r++) acc[r] = 0.f;
#pragma unroll 4
        for (int t = 0; t < 96; t++) {
            float p = __ldg(&pr[t * 96 + c]);
#pragma unroll
            for (int r = 0; r < 12; r++) acc[r] = fmaf(sws[r * 96 + t], p, acc[r]);
        }
#pragma unroll
        for (int r = 0; r < 12; r++)
            g_wbf[1][(jf0 + r) * 104 + c] = __float2bfloat16(acc[r]);
    } else {
        for (int r = tid; r < 288; r += 96) {
            const float* swr = sw + r * 96;
            float s = swb[r];
#pragma unroll 8
            for (int t = 0; t < 96; t++) s = fmaf(swr[t], prb[t], s);
            g_b1[r] = s;
        }
    }
}

// ---------------------------------------------------------------------------
// GEMM phase via ldmatrix + mma: warp computes D[16 x 96].
// aAddr/wAddr are per-thread ldmatrix base addresses (see call site).
// ---------------------------------------------------------------------------
__device__ __forceinline__ void hmma_phase(uint32_t aAddr, uint32_t wAddr,
                                           float acc[12][4])
{
#pragma unroll
    for (int nt = 0; nt < 12; nt++)
#pragma unroll
        for (int r = 0; r < 4; r++) acc[nt][r] = 0.f;
#pragma unroll
    for (int ks = 0; ks < 6; ks++) {
        uint32_t a0, a1, a2, a3;
        ldsm4(a0, a1, a2, a3, aAddr + ks * 32);
#pragma unroll
        for (int p = 0; p < 6; p++) {
            uint32_t b0, b1, b2, b3;
            ldsm4(b0, b1, b2, b3, wAddr + p * 3328 + ks * 32);
            asm volatile(
                "mma.sync.aligned.m16n8k16.row.col.f32.bf16.bf16.f32 "
                "{%0,%1,%2,%3}, {%4,%5,%6,%7}, {%8,%9}, {%0,%1,%2,%3};"
                : "+f"(acc[2*p][0]), "+f"(acc[2*p][1]), "+f"(acc[2*p][2]), "+f"(acc[2*p][3])
                : "r"(a0), "r"(a1), "r"(a2), "r"(a3), "r"(b0), "r"(b2));
            asm volatile(
                "mma.sync.aligned.m16n8k16.row.col.f32.bf16.bf16.f32 "
                "{%0,%1,%2,%3}, {%4,%5,%6,%7}, {%8,%9}, {%0,%1,%2,%3};"
                : "+f"(acc[2*p+1][0]), "+f"(acc[2*p+1][1]), "+f"(acc[2*p+1][2]), "+f"(acc[2*p+1][3])
                : "r"(a0), "r"(a1), "r"(a2), "r"(a3), "r"(b1), "r"(b3));
        }
    }
}

__device__ __forceinline__ void add_bias(const float* __restrict__ bias,
                                         int tig, float acc[12][4])
{
#pragma unroll
    for (int nt = 0; nt < 12; nt++) {
        float b0 = bias[nt * 8 + tig * 2], b1 = bias[nt * 8 + tig * 2 + 1];
        acc[nt][0] += b0; acc[nt][1] += b1; acc[nt][2] += b0; acc[nt][3] += b1;
    }
}

// stage one 96x104-bf16 weight image (19968B = 1248 x 16B) via cp.async
__device__ __forceinline__ void stage_w_async(uint32_t dst, const char* src, int tid)
{
    for (int f = tid; f < 1248; f += 256)
        CPA16(dst + f * 16, src + f * 16);
}

// ---------------------------------------------------------------------------
// Fused branch. Grid 256 x 256. Block = 64 position-groups x 2 frames.
// smem: tb 512 | qb 1152 | pb 384(+pad) | gt 2048 | gc 1024 | A 26624 | W x3
// ---------------------------------------------------------------------------
__global__ void __launch_bounds__(256, 2)
fused_branch(const float* __restrict__ xin_ext,
             const float* __restrict__ qkv_b_ext,
             const float* __restrict__ pr_b,
             float* __restrict__ out_ext,
             int branch, int shift)
{
    extern __shared__ char smem[];
    int*   tb = (int*)smem;                 // 128 token bases
    float* qb = (float*)(smem + 512);       // 288 qkv biases
    float* pb = (float*)(smem + 1664);      // 96 proj biases
    float* gt = (float*)(smem + 2048);      // 128 x 4 per-token G
    float* gc = (float*)(smem + 4096);      // 64 x 4 per-group G
    char*  smA = smem + 5120;               // [128][104] bf16 (x / o tile)
    char*  smW = smem + 31744;              // 3 x [96][104] bf16 slots

    uint32_t sb   = smem_u32(smem);
    uint32_t smAu = sb + 5120;
    uint32_t smWu = sb + 31744;

    int tid = threadIdx.x, w = tid >> 5, lane = tid & 31;
    int g = lane >> 2, tig = lane & 3;
    int l16 = lane & 15, lh = lane >> 4;
    int row0 = w * 16;

    const float* QB = branch ? g_b1 : qkv_b_ext;
    for (int i = tid; i < 288; i += 256) qb[i] = QB[i];
    if (branch && tid < 96) pb[tid] = pr_b[tid];

    if (tid < 128) {
        int pi = tid & 63;
        int gg = (blockIdx.x << 6) + pi;
        int b = gg >> 13, dw = (gg >> 10) & 7, p = gg & 1023;
        int d = (2 * dw + (tid >> 6) + shift) & 15;
        tb[tid] = ((b * 16 + d) * 1024 + p) * 96;
    }

    const char* WB = (const char*)g_wbf[branch];

    if (branch == 0) {
        // weights async (no tb dependency), A staged manually (fp32->bf16)
        stage_w_async(smWu,             WB + 96 * 208, tid); CPA_COMMIT();  // K
        stage_w_async(smWu + 19968,     WB + 192 * 208, tid); CPA_COMMIT(); // V
        stage_w_async(smWu + 2 * 19968, WB,             tid); CPA_COMMIT(); // Q
        __syncthreads();   // tb ready
        for (int f4 = tid; f4 < 3072; f4 += 256) {
            int l = f4 / 24, q4 = f4 % 24;
            float4 v = *(const float4*)&xin_ext[tb[l] + q4 * 4];
            __nv_bfloat162 p0 = __floats2bfloat162_rn(v.x, v.y);
            __nv_bfloat162 p1 = __floats2bfloat162_rn(v.z, v.w);
            *(uint2*)(smA + l * 208 + q4 * 8) =
                make_uint2(*(uint32_t*)&p0, *(uint32_t*)&p1);
        }
    } else {
        __syncthreads();   // tb ready
        for (int f = tid; f < 1536; f += 256) {       // A tile via cp.async
            int l = f / 12, u = f % 12;
            CPA16(smAu + l * 208 + u * 16,
                  (const char*)g_mid + (size_t)tb[l] * 2 + u * 16);
        }
        CPA_COMMIT();
        stage_w_async(smWu,             WB + 96 * 208, tid); CPA_COMMIT();  // K
        stage_w_async(smWu + 19968,     WB + 192 * 208, tid); CPA_COMMIT(); // V
        stage_w_async(smWu + 2 * 19968, WB,             tid); CPA_COMMIT(); // Q
    }

    // per-thread ldmatrix bases
    uint32_t aAddr = smAu + ((row0 + l16) * 104 + lh * 8) * 2;
    uint32_t wAddr = smWu + (l16 * 104 + lh * 8) * 2;

    float kacc[12][4], vacc[12][4];

    // ---- K ----  (branch0: K done after wait 2; branch1: A+K done)
    CPA_WAIT(2);
    __syncthreads();
    hmma_phase(aAddr, wAddr, kacc);
    add_bias(qb + 96, tig, kacc);

    // ---- V boundary: V arrived; slot0 free after barrier -> stage proj ----
    CPA_WAIT(1);
    __syncthreads();
    if (branch) { stage_w_async(smWu, (const char*)g_wpbf, tid); CPA_COMMIT(); }
    hmma_phase(aAddr, wAddr + 19968, vacc);
    add_bias(qb + 192, tig, vacc);

    // ---- per-token 2x2 G from k/v accumulator registers ----
    {
        float G[8];
#pragma unroll
        for (int i = 0; i < 8; i++) G[i] = 0.f;
#pragma unroll
        for (int nt = 0; nt < 12; nt++) {
            G[0] = fmaf(kacc[nt][0], vacc[nt][0], G[0]);
            G[1] = fmaf(kacc[nt][0], vacc[nt][1], G[1]);
            G[2] = fmaf(kacc[nt][1], vacc[nt][0], G[2]);
            G[3] = fmaf(kacc[nt][1], vacc[nt][1], G[3]);
            G[4] = fmaf(kacc[nt][2], vacc[nt][2], G[4]);
            G[5] = fmaf(kacc[nt][2], vacc[nt][3], G[5]);
            G[6] = fmaf(kacc[nt][3], vacc[nt][2], G[6]);
            G[7] = fmaf(kacc[nt][3], vacc[nt][3], G[7]);
        }
#pragma unroll
        for (int off = 1; off <= 2; off <<= 1)
#pragma unroll
            for (int i = 0; i < 8; i++)
                G[i] += __shfl_xor_sync(0xffffffffu, G[i], off);
        if (tig == 0) {
            *(float4*)&gt[(row0 + g) * 4]     = make_float4(G[0], G[1], G[2], G[3]);
            *(float4*)&gt[(row0 + g + 8) * 4] = make_float4(G[4], G[5], G[6], G[7]);
        }
    }
    __syncthreads();
    if (tid < 64) {
        float4 a = *(float4*)&gt[tid * 4];
        float4 b4 = *(float4*)&gt[(tid + 64) * 4];
        *(float4*)&gc[tid * 4] =
            make_float4(a.x + b4.x, a.y + b4.y, a.z + b4.z, a.w + b4.w);
    }
    if (branch) { CPA_WAIT(1); } else { CPA_WAIT(0); }   // Q weights arrived
    __syncthreads();

    // ---- Q (reuse kacc) + o = q @ G ----
    hmma_phase(aAddr, wAddr + 2 * 19968, kacc);
    add_bias(qb, tig, kacc);
    {
        float4 Glo = *(float4*)&gc[((row0 + g) & 63) * 4];
        float4 Ghi = *(float4*)&gc[((row0 + g + 8) & 63) * 4];
#pragma unroll
        for (int nt = 0; nt < 12; nt++) {
            int j0 = nt * 8 + tig * 2;
            float o0 = kacc[nt][0] * Glo.x + kacc[nt][1] * Glo.z;
            float o1 = kacc[nt][0] * Glo.y + kacc[nt][1] * Glo.w;
            float o2 = kacc[nt][2] * Ghi.x + kacc[nt][3] * Ghi.z;
            float o3 = kacc[nt][2] * Ghi.y + kacc[nt][3] * Ghi.w;
            __nv_bfloat162 plo = __floats2bfloat162_rn(o0, o1);
            __nv_bfloat162 phi = __floats2bfloat162_rn(o2, o3);
            *(uint32_t*)(smA + (row0 + g) * 208 + j0 * 2)     = *(uint32_t*)&plo;
            *(uint32_t*)(smA + (row0 + g + 8) * 208 + j0 * 2) = *(uint32_t*)&phi;
        }
    }

    if (branch == 0) {
        // ---- o tile -> g_mid (coalesced uint4 rows) ----
        __syncthreads();
        for (int f = tid; f < 1536; f += 256) {
            int l = f / 12, u = f % 12;
            *(uint4*)((char*)g_mid + (size_t)tb[l] * 2 + u * 16) =
                *(const uint4*)(smA + l * 208 + u * 16);
        }
    } else {
        // ---- proj: o tile @ projs_w^T + pb -> out ----
        // (each warp reads only its own smA rows, which it wrote itself;
        //  barrier only needed to publish proj weights)
        CPA_WAIT(0);
        __syncthreads();
        hmma_phase(aAddr, wAddr, kacc);
        int tbg = tb[row0 + g], tbh = tb[row0 + g + 8];
#pragma unroll
        for (int nt = 0; nt < 12; nt++) {
            int j0 = nt * 8 + tig * 2;
            float b0 = pb[j0], b1 = pb[j0 + 1];
            *(float2*)&out_ext[tbg + j0] =
                make_float2(kacc[nt][0] + b0, kacc[nt][1] + b1);
            *(float2*)&out_ext[tbh + j0] =
                make_float2(kacc[nt][2] + b0, kacc[nt][3] + b1);
        }
    }
}

// ---------------------------------------------------------------------------
extern "C" void kernel_launch(void* const* d_in, const int* in_sizes, int n_in,
                              void* d_out, int out_size)
{
    const float* x       = (const float*)d_in[0];
    const float* lr_w    = (const float*)d_in[1];
    const float* lr_b    = (const float*)d_in[2];
    const float* proj_w  = (const float*)d_in[3];
    const float* proj_b  = (const float*)d_in[4];
    const float* sw_w    = (const float*)d_in[5];
    const float* sw_b    = (const float*)d_in[6];
    const float* projs_w = (const float*)d_in[7];
    const float* projs_b = (const float*)d_in[8];
    float* out = (float*)d_out;

    cudaFuncSetAttribute(fused_branch,
                         cudaFuncAttributeMaxDynamicSharedMemorySize, SMEM_BYTES);

    prep_w<<<144, 256>>>(lr_w, projs_w);
    prep_fold<<<25, 96>>>(proj_w, sw_w, sw_b, proj_b);
    // branch 0: pairs (2w, 2w+1), x -> o0 (g_mid bf16); proj folded forward
    fused_branch<<<256, 256, SMEM_BYTES>>>(x, lr_b, nullptr, nullptr, 0, 0);
    // branch 1: pairs ((2w+15)&15, 2w); qkv' on o0, projs -> out
    fused_branch<<<256, 256, SMEM_BYTES>>>(nullptr, nullptr, projs_b, out, 1, 15);
}

// round 8
// speedup vs baseline: 3.9111x; 1.0244x over previous
#include <cuda_runtime.h>
#include <cuda_bf16.h>
#include <cstdint>

// ---------------------------------------------------------------------------
// TimemixingFC_channel, round 8: occupancy push (3 blocks/SM).
//   Algebra: per branch qkv = x@W^T + b; S=2 attention -> 2x2 G per
//   (position, window) group; o = q@G; proj. Branch-0 proj folded into
//   branch-1 qkv (W' = Wsw@Wp, b' = Wsw@bp + bsw). Rolls folded into pairing.
//   R8 vs R7 (latency-bound: occ 19.6%, tensor 23.4%, regs 125):
//     - per-n-tile-pair K/V processing folds k,v straight into the 8-reg G
//       accumulator (kills the 96-reg kacc/vacc pressure)
//     - A fragments cached once in 24 regs, reused by K, V and Q phases
//     - 2 weight smem slots (K/V, then re-staged Q/proj) -> 71.7KB smem
//     - __launch_bounds__(256,3): 3 blocks/SM, 24 warps/SM
// ---------------------------------------------------------------------------

#define SMEM_BYTES 71680

static __device__ __align__(16) __nv_bfloat16 g_mid[32768 * 96];   // o0 (bf16)
static __device__ __align__(16) __nv_bfloat16 g_wbf[2][288 * 104]; // qkv W, [jf][c] pad104
static __device__ __align__(16) __nv_bfloat16 g_wpbf[96 * 104];    // projs_w
static __device__ float g_b1[288];                                 // b' fold bias

// ---- PTX helpers (valid under compute_100) --------------------------------
__device__ __forceinline__ uint32_t smem_u32(const void* p) {
    uint32_t a;
    asm("{ .reg .u64 t; cvta.to.shared.u64 t, %1; cvt.u32.u64 %0, t; }" : "=r"(a) : "l"(p));
    return a;
}
#define CPA16(dst, src) \
    asm volatile("cp.async.cg.shared.global [%0], [%1], 16;" :: "r"(dst), "l"(src) : "memory")
#define CPA_COMMIT() asm volatile("cp.async.commit_group;" ::: "memory")
#define CPA_WAIT(n)  asm volatile("cp.async.wait_group %0;" :: "n"(n) : "memory")

__device__ __forceinline__ void ldsm4(uint32_t& r0, uint32_t& r1, uint32_t& r2,
                                      uint32_t& r3, uint32_t addr) {
    asm volatile("ldmatrix.sync.aligned.m8n8.x4.shared.b16 {%0,%1,%2,%3}, [%4];"
                 : "=r"(r0), "=r"(r1), "=r"(r2), "=r"(r3) : "r"(addr));
}
#define MMA(acc, a, b0, b1) \
    asm volatile("mma.sync.aligned.m16n8k16.row.col.f32.bf16.bf16.f32 " \
        "{%0,%1,%2,%3}, {%4,%5,%6,%7}, {%8,%9}, {%0,%1,%2,%3};" \
        : "+f"((acc)[0]), "+f"((acc)[1]), "+f"((acc)[2]), "+f"((acc)[3]) \
        : "r"((a)[0]), "r"((a)[1]), "r"((a)[2]), "r"((a)[3]), "r"(b0), "r"(b1))

// ---------------------------------------------------------------------------
// Merged prep. Grid 169 x 256.
//   [0,144):  bf16-convert lr_w -> g_wbf[0], projs_w -> g_wpbf
//   [144,168): W' = sw_w @ proj_w -> g_wbf[1] (fp32 math, bf16 store)
//   168:      b' = sw_w @ proj_b + sw_b -> g_b1
// ---------------------------------------------------------------------------
__global__ void prep_all(const float* __restrict__ lr,
                         const float* __restrict__ prs,
                         const float* __restrict__ pr,
                         const float* __restrict__ sw,
                         const float* __restrict__ swb,
                         const float* __restrict__ prb)
{
    int bid = blockIdx.x, tid = threadIdx.x;
    if (bid < 144) {
        int idx = bid * 256 + tid;   // < 36864
        if (idx < 27648) {
            int jf = idx / 96, c = idx % 96;
            g_wbf[0][jf * 104 + c] = __float2bfloat16(lr[idx]);
        } else {
            idx -= 27648;
            int j = idx / 96, c = idx % 96;
            g_wpbf[j * 104 + c] = __float2bfloat16(prs[idx]);
        }
    } else if (bid < 168) {
        __shared__ float sws[12 * 96];
        int jf0 = (bid - 144) * 12;
        for (int i = tid; i < 1152; i += 256) sws[i] = sw[jf0 * 96 + i];
        __syncthreads();
        if (tid < 96) {
            int c = tid;
            float acc[12];
#pragma unroll
            for (int r = 0; r < 12; r++) acc[r] = 0.f;
#pragma unroll 4
            for (int t = 0; t < 96; t++) {
                float p = __ldg(&pr[t * 96 + c]);
#pragma unroll
                for (int r = 0; r < 12; r++) acc[r] = fmaf(sws[r * 96 + t], p, acc[r]);
            }
#pragma unroll
            for (int r = 0; r < 12; r++)
                g_wbf[1][(jf0 + r) * 104 + c] = __float2bfloat16(acc[r]);
        }
    } else if (tid < 96) {
        for (int r = tid; r < 288; r += 96) {
            const float* swr = sw + r * 96;
            float s = swb[r];
#pragma unroll 8
            for (int t = 0; t < 96; t++) s = fmaf(swr[t], prb[t], s);
            g_b1[r] = s;
        }
    }
}

// ---------------------------------------------------------------------------
// One n-tile pair (tiles 2p, 2p+1): D[16 x 16] accumulated over K=96 with
// cached A fragments. acc[t][4] for t = tile-in-pair.
// ---------------------------------------------------------------------------
__device__ __forceinline__ void hmma_pair(const uint32_t af[6][4], uint32_t wAddr,
                                          int p, float acc[2][4])
{
#pragma unroll
    for (int t = 0; t < 2; t++)
#pragma unroll
        for (int r = 0; r < 4; r++) acc[t][r] = 0.f;
#pragma unroll
    for (int ks = 0; ks < 6; ks++) {
        uint32_t b0, b1, b2, b3;
        ldsm4(b0, b1, b2, b3, wAddr + p * 3328 + ks * 32);
        MMA(acc[0], af[ks], b0, b2);
        MMA(acc[1], af[ks], b1, b3);
    }
}

// stage one 96x104-bf16 weight image (19968B = 1248 x 16B) via cp.async
__device__ __forceinline__ void stage_w_async(uint32_t dst, const char* src, int tid)
{
    for (int f = tid; f < 1248; f += 256)
        CPA16(dst + f * 16, src + f * 16);
}

// ---------------------------------------------------------------------------
// Fused branch. Grid 256 x 256. Block = 64 position-groups x 2 frames.
// smem: tb 512 | qb 1152 | pb 384 | gt 2048 | gc 1024 | A 26624 | W x2 39936
// ---------------------------------------------------------------------------
__global__ void __launch_bounds__(256, 3)
fused_branch(const float* __restrict__ xin_ext,
             const float* __restrict__ qkv_b_ext,
             const float* __restrict__ pr_b,
             float* __restrict__ out_ext,
             int branch, int shift)
{
    extern __shared__ char smem[];
    int*   tb = (int*)smem;                 // 128 token bases
    float* qb = (float*)(smem + 512);       // 288 qkv biases
    float* pb = (float*)(smem + 1664);      // 96 proj biases
    float* gt = (float*)(smem + 2048);      // 128 x 4 per-token G
    float* gc = (float*)(smem + 4096);      // 64 x 4 per-group G
    char*  smA = smem + 5120;               // [128][104] bf16 (x / o tile)

    uint32_t sb   = smem_u32(smem);
    uint32_t smAu = sb + 5120;
    uint32_t smWu = sb + 31744;             // 2 x [96][104] bf16 slots

    int tid = threadIdx.x, w = tid >> 5, lane = tid & 31;
    int g = lane >> 2, tig = lane & 3;
    int l16 = lane & 15, lh = lane >> 4;
    int row0 = w * 16;

    const float* QB = branch ? g_b1 : qkv_b_ext;
    for (int i = tid; i < 288; i += 256) qb[i] = QB[i];
    if (branch && tid < 96) pb[tid] = pr_b[tid];

    if (tid < 128) {
        int pi = tid & 63;
        int gg = (blockIdx.x << 6) + pi;
        int b = gg >> 13, dw = (gg >> 10) & 7, p = gg & 1023;
        int d = (2 * dw + (tid >> 6) + shift) & 15;
        tb[tid] = ((b * 16 + d) * 1024 + p) * 96;
    }

    const char* WB = (const char*)g_wbf[branch];

    if (branch == 0) {
        stage_w_async(smWu,         WB + 96 * 208, tid);  // K -> slot0
        stage_w_async(smWu + 19968, WB + 192 * 208, tid); // V -> slot1
        CPA_COMMIT();
        __syncthreads();   // tb ready
        for (int f4 = tid; f4 < 3072; f4 += 256) {
            int l = f4 / 24, q4 = f4 % 24;
            float4 v = *(const float4*)&xin_ext[tb[l] + q4 * 4];
            __nv_bfloat162 p0 = __floats2bfloat162_rn(v.x, v.y);
            __nv_bfloat162 p1 = __floats2bfloat162_rn(v.z, v.w);
            *(uint2*)(smA + l * 208 + q4 * 8) =
                make_uint2(*(uint32_t*)&p0, *(uint32_t*)&p1);
        }
    } else {
        __syncthreads();   // tb ready
        for (int f = tid; f < 1536; f += 256) {       // A tile via cp.async
            int l = f / 12, u = f % 12;
            CPA16(smAu + l * 208 + u * 16,
                  (const char*)g_mid + (size_t)tb[l] * 2 + u * 16);
        }
        stage_w_async(smWu,         WB + 96 * 208, tid);  // K
        stage_w_async(smWu + 19968, WB + 192 * 208, tid); // V
        CPA_COMMIT();
    }

    uint32_t aAddr = smAu + ((row0 + l16) * 104 + lh * 8) * 2;
    uint32_t wAddr = smWu + (l16 * 104 + lh * 8) * 2;

    CPA_WAIT(0);
    __syncthreads();        // A + K + V visible

    // ---- cache A fragments (reused by K, V, Q) ----
    uint32_t af[6][4];
#pragma unroll
    for (int ks = 0; ks < 6; ks++)
        ldsm4(af[ks][0], af[ks][1], af[ks][2], af[ks][3], aAddr + ks * 32);

    // ---- K/V per pair, folded into per-token 2x2 G ----
    float G[8];
#pragma unroll
    for (int i = 0; i < 8; i++) G[i] = 0.f;
#pragma unroll
    for (int p = 0; p < 6; p++) {
        float ka[2][4], va[2][4];
        hmma_pair(af, wAddr, p, ka);
        hmma_pair(af, wAddr + 19968, p, va);
#pragma unroll
        for (int t = 0; t < 2; t++) {
            int j0 = (2 * p + t) * 8 + tig * 2;
            float kb0 = qb[96 + j0], kb1 = qb[96 + j0 + 1];
            float vb0 = qb[192 + j0], vb1 = qb[192 + j0 + 1];
            float k0 = ka[t][0] + kb0, k1 = ka[t][1] + kb1;
            float k2 = ka[t][2] + kb0, k3 = ka[t][3] + kb1;
            float v0 = va[t][0] + vb0, v1 = va[t][1] + vb1;
            float v2 = va[t][2] + vb0, v3 = va[t][3] + vb1;
            G[0] = fmaf(k0, v0, G[0]); G[1] = fmaf(k0, v1, G[1]);
            G[2] = fmaf(k1, v0, G[2]); G[3] = fmaf(k1, v1, G[3]);
            G[4] = fmaf(k2, v2, G[4]); G[5] = fmaf(k2, v3, G[5]);
            G[6] = fmaf(k3, v2, G[6]); G[7] = fmaf(k3, v3, G[7]);
        }
    }
    __syncthreads();        // all warps done with K/V weight slots

    // re-stage slot0 = Q weights, slot1 = proj weights (branch1)
    stage_w_async(smWu, WB, tid);
    if (branch) stage_w_async(smWu + 19968, (const char*)g_wpbf, tid);
    CPA_COMMIT();

    // ---- reduce G across the 4 lanes of each row, then across frame pair ----
#pragma unroll
    for (int off = 1; off <= 2; off <<= 1)
#pragma unroll
        for (int i = 0; i < 8; i++)
            G[i] += __shfl_xor_sync(0xffffffffu, G[i], off);
    if (tig == 0) {
        *(float4*)&gt[(row0 + g) * 4]     = make_float4(G[0], G[1], G[2], G[3]);
        *(float4*)&gt[(row0 + g + 8) * 4] = make_float4(G[4], G[5], G[6], G[7]);
    }
    __syncthreads();
    if (tid < 64) {
        float4 a = *(float4*)&gt[tid * 4];
        float4 b4 = *(float4*)&gt[(tid + 64) * 4];
        *(float4*)&gc[tid * 4] =
            make_float4(a.x + b4.x, a.y + b4.y, a.z + b4.z, a.w + b4.w);
    }
    CPA_WAIT(0);
    __syncthreads();        // gc + Q (+proj) weights visible

    float4 Glo = *(float4*)&gc[((row0 + g) & 63) * 4];
    float4 Ghi = *(float4*)&gc[((row0 + g + 8) & 63) * 4];

    // ---- Q per pair + o = q @ G -> bf16 into own smA rows ----
#pragma unroll
    for (int p = 0; p < 6; p++) {
        float qa[2][4];
        hmma_pair(af, wAddr, p, qa);
#pragma unroll
        for (int t = 0; t < 2; t++) {
            int j0 = (2 * p + t) * 8 + tig * 2;
            float b0 = qb[j0], b1 = qb[j0 + 1];
            float q0 = qa[t][0] + b0, q1 = qa[t][1] + b1;
            float q2 = qa[t][2] + b0, q3 = qa[t][3] + b1;
            float o0 = q0 * Glo.x + q1 * Glo.z;
            float o1 = q0 * Glo.y + q1 * Glo.w;
            float o2 = q2 * Ghi.x + q3 * Ghi.z;
            float o3 = q2 * Ghi.y + q3 * Ghi.w;
            __nv_bfloat162 plo = __floats2bfloat162_rn(o0, o1);
            __nv_bfloat162 phi = __floats2bfloat162_rn(o2, o3);
            *(uint32_t*)(smA + (row0 + g) * 208 + j0 * 2)     = *(uint32_t*)&plo;
            *(uint32_t*)(smA + (row0 + g + 8) * 208 + j0 * 2) = *(uint32_t*)&phi;
        }
    }

    if (branch == 0) {
        // ---- o tile -> g_mid (coalesced uint4 rows) ----
        __syncthreads();
        for (int f = tid; f < 1536; f += 256) {
            int l = f / 12, u = f % 12;
            *(uint4*)((char*)g_mid + (size_t)tb[l] * 2 + u * 16) =
                *(const uint4*)(smA + l * 208 + u * 16);
        }
    } else {
        // ---- proj: o tile @ projs_w^T + pb -> out (warp-local A rows) ----
        __syncwarp();       // order own-warp STS -> LDSM
#pragma unroll
        for (int ks = 0; ks < 6; ks++)
            ldsm4(af[ks][0], af[ks][1], af[ks][2], af[ks][3], aAddr + ks * 32);
        int tbg = tb[row0 + g], tbh = tb[row0 + g + 8];
#pragma unroll
        for (int p = 0; p < 6; p++) {
            float pa[2][4];
            hmma_pair(af, wAddr + 19968, p, pa);
#pragma unroll
            for (int t = 0; t < 2; t++) {
                int j0 = (2 * p + t) * 8 + tig * 2;
                float b0 = pb[j0], b1 = pb[j0 + 1];
                *(float2*)&out_ext[tbg + j0] =
                    make_float2(pa[t][0] + b0, pa[t][1] + b1);
                *(float2*)&out_ext[tbh + j0] =
                    make_float2(pa[t][2] + b0, pa[t][3] + b1);
            }
        }
    }
}

// ---------------------------------------------------------------------------
extern "C" void kernel_launch(void* const* d_in, const int* in_sizes, int n_in,
                              void* d_out, int out_size)
{
    const float* x       = (const float*)d_in[0];
    const float* lr_w    = (const float*)d_in[1];
    const float* lr_b    = (const float*)d_in[2];
    const float* proj_w  = (const float*)d_in[3];
    const float* proj_b  = (const float*)d_in[4];
    const float* sw_w    = (const float*)d_in[5];
    const float* sw_b    = (const float*)d_in[6];
    const float* projs_w = (const float*)d_in[7];
    const float* projs_b = (const float*)d_in[8];
    float* out = (float*)d_out;

    cudaFuncSetAttribute(fused_branch,
                         cudaFuncAttributeMaxDynamicSharedMemorySize, SMEM_BYTES);

    prep_all<<<169, 256>>>(lr_w, projs_w, proj_w, sw_w, sw_b, proj_b);
    // branch 0: pairs (2w, 2w+1), x -> o0 (g_mid bf16); proj folded forward
    fused_branch<<<256, 256, SMEM_BYTES>>>(x, lr_b, nullptr, nullptr, 0, 0);
    // branch 1: pairs ((2w+15)&15, 2w); qkv' on o0, projs -> out
    fused_branch<<<256, 256, SMEM_BYTES>>>(nullptr, nullptr, projs_b, out, 1, 15);
}

// round 11
// speedup vs baseline: 4.7067x; 1.2034x over previous
#include <cuda_runtime.h>
#include <cuda_bf16.h>
#include <cstdint>

// ---------------------------------------------------------------------------
// TimemixingFC_channel, round 11: R8 hot path + fast standalone prep.
//   Algebra: per branch qkv = x@W^T + b; S=2 attention -> 2x2 G per
//   (position, window) group; o = q@G; proj. Branch-0 proj folded into
//   branch-1 qkv (W' = Wsw@Wp, b' = Wsw@bp + bsw). Rolls folded into pairing.
//   vs R8 (prep_all was 21.4us = 45% of runtime):
//     - prep_tr: bf16 transposes only (144 x 256, 1 elem/thread, ~1.5us)
//     - prep_fold: W'/b' fold as 19 register-tiled blocks (256 thr, smem-
//       staged operands, 6 outputs/thread) instead of 96-thr serial-__ldg
//       blocks (~2.5us vs 21us).
//   Fused kernel byte-identical to R8's (per-pair K/V -> G, cached A
//   fragments, 2 cp.async weight slots, 3 blocks/SM, grid 256 = 1 wave).
// ---------------------------------------------------------------------------

#define SMEM_BYTES 71680

static __device__ __align__(16) __nv_bfloat16 g_mid[32768 * 96];   // o0 (bf16)
static __device__ __align__(16) __nv_bfloat16 g_wbf[2][288 * 104]; // qkv W, [jf][c] pad104
static __device__ __align__(16) __nv_bfloat16 g_wpbf[96 * 104];    // projs_w
static __device__ float g_b1[288];                                 // b' fold bias

// ---- PTX helpers (valid under compute_100) --------------------------------
__device__ __forceinline__ uint32_t smem_u32(const void* p) {
    uint32_t a;
    asm("{ .reg .u64 t; cvta.to.shared.u64 t, %1; cvt.u32.u64 %0, t; }" : "=r"(a) : "l"(p));
    return a;
}
#define CPA16(dst, src) \
    asm volatile("cp.async.cg.shared.global [%0], [%1], 16;" :: "r"(dst), "l"(src) : "memory")
#define CPA_COMMIT() asm volatile("cp.async.commit_group;" ::: "memory")
#define CPA_WAIT(n)  asm volatile("cp.async.wait_group %0;" :: "n"(n) : "memory")

__device__ __forceinline__ void ldsm4(uint32_t& r0, uint32_t& r1, uint32_t& r2,
                                      uint32_t& r3, uint32_t addr) {
    asm volatile("ldmatrix.sync.aligned.m8n8.x4.shared.b16 {%0,%1,%2,%3}, [%4];"
                 : "=r"(r0), "=r"(r1), "=r"(r2), "=r"(r3) : "r"(addr));
}
#define MMA(acc, a, b0, b1) \
    asm volatile("mma.sync.aligned.m16n8k16.row.col.f32.bf16.bf16.f32 " \
        "{%0,%1,%2,%3}, {%4,%5,%6,%7}, {%8,%9}, {%0,%1,%2,%3};" \
        : "+f"((acc)[0]), "+f"((acc)[1]), "+f"((acc)[2]), "+f"((acc)[3]) \
        : "r"((a)[0]), "r"((a)[1]), "r"((a)[2]), "r"((a)[3]), "r"(b0), "r"(b1))

// ---------------------------------------------------------------------------
// Prep 1: bf16 transposes only. Grid 144 x 256, 1 elem/thread.
// ---------------------------------------------------------------------------
__global__ void prep_tr(const float* __restrict__ lr,
                        const float* __restrict__ prs)
{
    int idx = blockIdx.x * 256 + threadIdx.x;   // < 36864
    if (idx < 27648) {
        int jf = idx / 96, c = idx % 96;
        g_wbf[0][jf * 104 + c] = __float2bfloat16(lr[idx]);
    } else {
        int i2 = idx - 27648;
        int j = i2 / 96, c = i2 % 96;
        g_wpbf[j * 104 + c] = __float2bfloat16(prs[i2]);
    }
}

// ---------------------------------------------------------------------------
// Prep 2: W' = sw_w @ proj_w -> g_wbf[1] (fp32 math, bf16 store), and
// b' = sw_w @ proj_b + sw_b -> g_b1. Grid 19 x 256.
//   blocks 0..17: 16 rows of W' each; 256 thr = 16 rows x 16 col-groups,
//                 6 outputs/thread, operands staged in smem.
//   block 18:     b' (288 rows, one warp-shfl free reduction per row group).
// ---------------------------------------------------------------------------
__global__ void prep_fold(const float* __restrict__ pr,    // proj_w
                          const float* __restrict__ sw,    // sw_w
                          const float* __restrict__ swb,   // sw_b
                          const float* __restrict__ prb)   // proj_b
{
    __shared__ float prs[96 * 100];   // proj_w padded (38400B)
    __shared__ float sws[16 * 96];    // 16 sw rows     (6144B)
    int bid = blockIdx.x, tid = threadIdx.x;

    if (bid < 18) {
        int jf0 = bid * 16;
        for (int i = tid; i < 2304; i += 256) {
            int t = i / 24, c4 = (i % 24) * 4;
            *(float4*)&prs[t * 100 + c4] = *(const float4*)&pr[t * 96 + c4];
        }
        for (int i = tid; i < 1536; i += 256)
            sws[i] = sw[jf0 * 96 + i];
        __syncthreads();

        int rgrp = tid >> 4, cgrp = tid & 15;
        int c0 = cgrp * 6;
        const float* swr = &sws[rgrp * 96];
        float acc[6];
#pragma unroll
        for (int j = 0; j < 6; j++) acc[j] = 0.f;
#pragma unroll 4
        for (int t = 0; t < 96; t++) {
            float s = swr[t];
#pragma unroll
            for (int j = 0; j < 6; j++)
                acc[j] = fmaf(s, prs[t * 100 + c0 + j], acc[j]);
        }
        int jf = jf0 + rgrp;
#pragma unroll
        for (int j = 0; j < 6; j++)
            g_wbf[1][jf * 104 + c0 + j] = __float2bfloat16(acc[j]);
    } else {
        // b': 256 thr = 16 rows x 16 lanes; 2 passes cover 288 rows
        if (tid < 96) sws[tid] = prb[tid];     // reuse sws as prb buffer
        __syncthreads();
        int rgrp = tid >> 4, cgrp = tid & 15;
        int c0 = cgrp * 6;
        for (int pass = 0; pass < 18; pass += 16) {
            int r = (pass + rgrp < 18) ? (pass / 16) * 256 + rgrp * 16 : -1;
            (void)r;
        }
        // simpler: each of 16 rgrp handles rows rgrp, rgrp+16, ..., < 288
        for (int r = rgrp; r < 288; r += 16) {
            const float* swr = sw + r * 96;
            float pacc = 0.f;
#pragma unroll
            for (int t = 0; t < 6; t++)
                pacc = fmaf(swr[c0 + t], sws[c0 + t], pacc);
#pragma unroll
            for (int off = 1; off < 16; off <<= 1)
                pacc += __shfl_xor_sync(0xffffffffu, pacc, off);
            if (cgrp == 0) g_b1[r] = pacc + swb[r];
        }
    }
}

// ---------------------------------------------------------------------------
// One n-tile pair (tiles 2p, 2p+1): D[16 x 16] accumulated over K=96 with
// cached A fragments.
// ---------------------------------------------------------------------------
__device__ __forceinline__ void hmma_pair(const uint32_t af[6][4], uint32_t wAddr,
                                          int p, float acc[2][4])
{
#pragma unroll
    for (int t = 0; t < 2; t++)
#pragma unroll
        for (int r = 0; r < 4; r++) acc[t][r] = 0.f;
#pragma unroll
    for (int ks = 0; ks < 6; ks++) {
        uint32_t b0, b1, b2, b3;
        ldsm4(b0, b1, b2, b3, wAddr + p * 3328 + ks * 32);
        MMA(acc[0], af[ks], b0, b2);
        MMA(acc[1], af[ks], b1, b3);
    }
}

// stage one 96x104-bf16 weight image (19968B = 1248 x 16B) via cp.async
__device__ __forceinline__ void stage_w_async(uint32_t dst, const char* src, int tid)
{
    for (int f = tid; f < 1248; f += 256)
        CPA16(dst + f * 16, src + f * 16);
}

// ---------------------------------------------------------------------------
// Fused branch (identical to R8). Grid 256 x 256.
// Block = 64 position-groups x 2 frames.
// ---------------------------------------------------------------------------
__global__ void __launch_bounds__(256, 3)
fused_branch(const float* __restrict__ xin_ext,
             const float* __restrict__ qkv_b_ext,
             const float* __restrict__ pr_b,
             float* __restrict__ out_ext,
             int branch, int shift)
{
    extern __shared__ char smem[];
    int*   tb = (int*)smem;                 // 128 token bases
    float* qb = (float*)(smem + 512);       // 288 qkv biases
    float* pb = (float*)(smem + 1664);      // 96 proj biases
    float* gt = (float*)(smem + 2048);      // 128 x 4 per-token G
    float* gc = (float*)(smem + 4096);      // 64 x 4 per-group G
    char*  smA = smem + 5120;               // [128][104] bf16 (x / o tile)

    uint32_t sb   = smem_u32(smem);
    uint32_t smAu = sb + 5120;
    uint32_t smWu = sb + 31744;             // 2 x [96][104] bf16 slots

    int tid = threadIdx.x, w = tid >> 5, lane = tid & 31;
    int g = lane >> 2, tig = lane & 3;
    int l16 = lane & 15, lh = lane >> 4;
    int row0 = w * 16;

    const float* QB = branch ? g_b1 : qkv_b_ext;
    for (int i = tid; i < 288; i += 256) qb[i] = QB[i];
    if (branch && tid < 96) pb[tid] = pr_b[tid];

    if (tid < 128) {
        int pi = tid & 63;
        int gg = (blockIdx.x << 6) + pi;
        int b = gg >> 13, dw = (gg >> 10) & 7, p = gg & 1023;
        int d = (2 * dw + (tid >> 6) + shift) & 15;
        tb[tid] = ((b * 16 + d) * 1024 + p) * 96;
    }

    const char* WB = (const char*)g_wbf[branch];

    if (branch == 0) {
        stage_w_async(smWu,         WB + 96 * 208, tid);  // K -> slot0
        stage_w_async(smWu + 19968, WB + 192 * 208, tid); // V -> slot1
        CPA_COMMIT();
        __syncthreads();   // tb ready
        for (int f4 = tid; f4 < 3072; f4 += 256) {
            int l = f4 / 24, q4 = f4 % 24;
            float4 v = *(const float4*)&xin_ext[tb[l] + q4 * 4];
            __nv_bfloat162 p0 = __floats2bfloat162_rn(v.x, v.y);
            __nv_bfloat162 p1 = __floats2bfloat162_rn(v.z, v.w);
            *(uint2*)(smA + l * 208 + q4 * 8) =
                make_uint2(*(uint32_t*)&p0, *(uint32_t*)&p1);
        }
    } else {
        __syncthreads();   // tb ready
        for (int f = tid; f < 1536; f += 256) {       // A tile via cp.async
            int l = f / 12, u = f % 12;
            CPA16(smAu + l * 208 + u * 16,
                  (const char*)g_mid + (size_t)tb[l] * 2 + u * 16);
        }
        stage_w_async(smWu,         WB + 96 * 208, tid);  // K
        stage_w_async(smWu + 19968, WB + 192 * 208, tid); // V
        CPA_COMMIT();
    }

    uint32_t aAddr = smAu + ((row0 + l16) * 104 + lh * 8) * 2;
    uint32_t wAddr = smWu + (l16 * 104 + lh * 8) * 2;

    CPA_WAIT(0);
    __syncthreads();        // A + K + V visible

    // ---- cache A fragments (reused by K, V, Q) ----
    uint32_t af[6][4];
#pragma unroll
    for (int ks = 0; ks < 6; ks++)
        ldsm4(af[ks][0], af[ks][1], af[ks][2], af[ks][3], aAddr + ks * 32);

    // ---- K/V per pair, folded into per-token 2x2 G ----
    float G[8];
#pragma unroll
    for (int i = 0; i < 8; i++) G[i] = 0.f;
#pragma unroll
    for (int p = 0; p < 6; p++) {
        float ka[2][4], va[2][4];
        hmma_pair(af, wAddr, p, ka);
        hmma_pair(af, wAddr + 19968, p, va);
#pragma unroll
        for (int t = 0; t < 2; t++) {
            int j0 = (2 * p + t) * 8 + tig * 2;
            float kb0 = qb[96 + j0], kb1 = qb[96 + j0 + 1];
            float vb0 = qb[192 + j0], vb1 = qb[192 + j0 + 1];
            float k0 = ka[t][0] + kb0, k1 = ka[t][1] + kb1;
            float k2 = ka[t][2] + kb0, k3 = ka[t][3] + kb1;
            float v0 = va[t][0] + vb0, v1 = va[t][1] + vb1;
            float v2 = va[t][2] + vb0, v3 = va[t][3] + vb1;
            G[0] = fmaf(k0, v0, G[0]); G[1] = fmaf(k0, v1, G[1]);
            G[2] = fmaf(k1, v0, G[2]); G[3] = fmaf(k1, v1, G[3]);
            G[4] = fmaf(k2, v2, G[4]); G[5] = fmaf(k2, v3, G[5]);
            G[6] = fmaf(k3, v2, G[6]); G[7] = fmaf(k3, v3, G[7]);
        }
    }
    __syncthreads();        // all warps done with K/V weight slots

    // re-stage slot0 = Q weights, slot1 = proj weights (branch1)
    stage_w_async(smWu, WB, tid);
    if (branch) stage_w_async(smWu + 19968, (const char*)g_wpbf, tid);
    CPA_COMMIT();

    // ---- reduce G across 4 lanes of each row, then across frame pair ----
#pragma unroll
    for (int off = 1; off <= 2; off <<= 1)
#pragma unroll
        for (int i = 0; i < 8; i++)
            G[i] += __shfl_xor_sync(0xffffffffu, G[i], off);
    if (tig == 0) {
        *(float4*)&gt[(row0 + g) * 4]     = make_float4(G[0], G[1], G[2], G[3]);
        *(float4*)&gt[(row0 + g + 8) * 4] = make_float4(G[4], G[5], G[6], G[7]);
    }
    __syncthreads();
    if (tid < 64) {
        float4 a = *(float4*)&gt[tid * 4];
        float4 b4 = *(float4*)&gt[(tid + 64) * 4];
        *(float4*)&gc[tid * 4] =
            make_float4(a.x + b4.x, a.y + b4.y, a.z + b4.z, a.w + b4.w);
    }
    CPA_WAIT(0);
    __syncthreads();        // gc + Q (+proj) weights visible

    float4 Glo = *(float4*)&gc[((row0 + g) & 63) * 4];
    float4 Ghi = *(float4*)&gc[((row0 + g + 8) & 63) * 4];

    // ---- Q per pair + o = q @ G -> bf16 into own smA rows ----
#pragma unroll
    for (int p = 0; p < 6; p++) {
        float qa[2][4];
        hmma_pair(af, wAddr, p, qa);
#pragma unroll
        for (int t = 0; t < 2; t++) {
            int j0 = (2 * p + t) * 8 + tig * 2;
            float b0 = qb[j0], b1 = qb[j0 + 1];
            float q0 = qa[t][0] + b0, q1 = qa[t][1] + b1;
            float q2 = qa[t][2] + b0, q3 = qa[t][3] + b1;
            float o0 = q0 * Glo.x + q1 * Glo.z;
            float o1 = q0 * Glo.y + q1 * Glo.w;
            float o2 = q2 * Ghi.x + q3 * Ghi.z;
            float o3 = q2 * Ghi.y + q3 * Ghi.w;
            __nv_bfloat162 plo = __floats2bfloat162_rn(o0, o1);
            __nv_bfloat162 phi = __floats2bfloat162_rn(o2, o3);
            *(uint32_t*)(smA + (row0 + g) * 208 + j0 * 2)     = *(uint32_t*)&plo;
            *(uint32_t*)(smA + (row0 + g + 8) * 208 + j0 * 2) = *(uint32_t*)&phi;
        }
    }

    if (branch == 0) {
        // ---- o tile -> g_mid (coalesced uint4 rows) ----
        __syncthreads();
        for (int f = tid; f < 1536; f += 256) {
            int l = f / 12, u = f % 12;
            *(uint4*)((char*)g_mid + (size_t)tb[l] * 2 + u * 16) =
                *(const uint4*)(smA + l * 208 + u * 16);
        }
    } else {
        // ---- proj: o tile @ projs_w^T + pb -> out (warp-local A rows) ----
        __syncwarp();       // order own-warp STS -> LDSM
#pragma unroll
        for (int ks = 0; ks < 6; ks++)
            ldsm4(af[ks][0], af[ks][1], af[ks][2], af[ks][3], aAddr + ks * 32);
        int tbg = tb[row0 + g], tbh = tb[row0 + g + 8];
#pragma unroll
        for (int p = 0; p < 6; p++) {
            float pa[2][4];
            hmma_pair(af, wAddr + 19968, p, pa);
#pragma unroll
            for (int t = 0; t < 2; t++) {
                int j0 = (2 * p + t) * 8 + tig * 2;
                float b0 = pb[j0], b1 = pb[j0 + 1];
                *(float2*)&out_ext[tbg + j0] =
                    make_float2(pa[t][0] + b0, pa[t][1] + b1);
                *(float2*)&out_ext[tbh + j0] =
                    make_float2(pa[t][2] + b0, pa[t][3] + b1);
            }
        }
    }
}

// ---------------------------------------------------------------------------
extern "C" void kernel_launch(void* const* d_in, const int* in_sizes, int n_in,
                              void* d_out, int out_size)
{
    const float* x       = (const float*)d_in[0];
    const float* lr_w    = (const float*)d_in[1];
    const float* lr_b    = (const float*)d_in[2];
    const float* proj_w  = (const float*)d_in[3];
    const float* proj_b  = (const float*)d_in[4];
    const float* sw_w    = (const float*)d_in[5];
    const float* sw_b    = (const float*)d_in[6];
    const float* projs_w = (const float*)d_in[7];
    const float* projs_b = (const float*)d_in[8];
    float* out = (float*)d_out;

    cudaFuncSetAttribute(fused_branch,
                         cudaFuncAttributeMaxDynamicSharedMemorySize, SMEM_BYTES);

    prep_tr<<<144, 256>>>(lr_w, projs_w);
    prep_fold<<<19, 256>>>(proj_w, sw_w, sw_b, proj_b);
    // branch 0: pairs (2w, 2w+1), x -> o0 (g_mid bf16); proj folded forward
    fused_branch<<<256, 256, SMEM_BYTES>>>(x, lr_b, nullptr, nullptr, 0, 0);
    // branch 1: pairs ((2w+15)&15, 2w); qkv' on o0, projs -> out
    fused_branch<<<256, 256, SMEM_BYTES>>>(nullptr, nullptr, projs_b, out, 1, 15);
}

// round 12
// speedup vs baseline: 4.7338x; 1.0058x over previous
#include <cuda_runtime.h>
#include <cuda_bf16.h>
#include <cstdint>

// ---------------------------------------------------------------------------
// TimemixingFC_channel, round 12: mega-phase (K/V/Q in one loop, Q held in
// registers until G is ready).
//   Algebra: per branch qkv = x@W^T + b; S=2 attention -> 2x2 G per
//   (position, window) group; o = q@G; proj. Branch-0 proj folded into
//   branch-1 qkv (W' = Wsw@Wp, b' = Wsw@bp + bsw). Rolls folded into pairing.
//   vs R11 (fused 17.9us, issue 30%, latency-bound; occ-3 unreachable at
//   grid 256):
//     - 3 pre-staged weight slots; single main loop issues K, V and Q MMA
//       chains per n-tile pair (~6 independent HMMA chains in flight) and
//       folds K/V straight into G; Q accumulators persist in 48 regs.
//     - one fewer phase boundary / sync; proj weights re-stage during the
//       G reduction.
//     - prep merged into a single kernel launch (163 blocks).
// Grid 256 x 256thr, 91.6KB smem, 2 blocks/SM.
// ---------------------------------------------------------------------------

#define SMEM_BYTES 91648

static __device__ __align__(16) __nv_bfloat16 g_mid[32768 * 96];   // o0 (bf16)
static __device__ __align__(16) __nv_bfloat16 g_wbf[2][288 * 104]; // qkv W, [jf][c] pad104
static __device__ __align__(16) __nv_bfloat16 g_wpbf[96 * 104];    // projs_w
static __device__ float g_b1[288];                                 // b' fold bias

// ---- PTX helpers (valid under compute_100) --------------------------------
__device__ __forceinline__ uint32_t smem_u32(const void* p) {
    uint32_t a;
    asm("{ .reg .u64 t; cvta.to.shared.u64 t, %1; cvt.u32.u64 %0, t; }" : "=r"(a) : "l"(p));
    return a;
}
#define CPA16(dst, src) \
    asm volatile("cp.async.cg.shared.global [%0], [%1], 16;" :: "r"(dst), "l"(src) : "memory")
#define CPA_COMMIT() asm volatile("cp.async.commit_group;" ::: "memory")
#define CPA_WAIT(n)  asm volatile("cp.async.wait_group %0;" :: "n"(n) : "memory")

__device__ __forceinline__ void ldsm4(uint32_t& r0, uint32_t& r1, uint32_t& r2,
                                      uint32_t& r3, uint32_t addr) {
    asm volatile("ldmatrix.sync.aligned.m8n8.x4.shared.b16 {%0,%1,%2,%3}, [%4];"
                 : "=r"(r0), "=r"(r1), "=r"(r2), "=r"(r3) : "r"(addr));
}
#define MMA(acc, a, b0, b1) \
    asm volatile("mma.sync.aligned.m16n8k16.row.col.f32.bf16.bf16.f32 " \
        "{%0,%1,%2,%3}, {%4,%5,%6,%7}, {%8,%9}, {%0,%1,%2,%3};" \
        : "+f"((acc)[0]), "+f"((acc)[1]), "+f"((acc)[2]), "+f"((acc)[3]) \
        : "r"((a)[0]), "r"((a)[1]), "r"((a)[2]), "r"((a)[3]), "r"(b0), "r"(b1))

// ---------------------------------------------------------------------------
// Merged prep. Grid 163 x 256.
//   [0,144):   bf16 transposes (lr_w -> g_wbf[0], projs_w -> g_wpbf)
//   [144,162): 16 rows of W' = sw @ pr each (register-tiled, smem operands)
//   162:       b' = sw @ prb + swb
// ---------------------------------------------------------------------------
__global__ void prep_all(const float* __restrict__ lr,
                         const float* __restrict__ prs,
                         const float* __restrict__ pr,
                         const float* __restrict__ sw,
                         const float* __restrict__ swb,
                         const float* __restrict__ prb)
{
    __shared__ float prs_s[96 * 100];
    __shared__ float sws[16 * 96];
    int bid = blockIdx.x, tid = threadIdx.x;

    if (bid < 144) {
        int idx = bid * 256 + tid;   // < 36864
        if (idx < 27648) {
            int jf = idx / 96, c = idx % 96;
            g_wbf[0][jf * 104 + c] = __float2bfloat16(lr[idx]);
        } else {
            int i2 = idx - 27648;
            int j = i2 / 96, c = i2 % 96;
            g_wpbf[j * 104 + c] = __float2bfloat16(prs[i2]);
        }
    } else if (bid < 162) {
        int jf0 = (bid - 144) * 16;
        for (int i = tid; i < 2304; i += 256) {
            int t = i / 24, c4 = (i % 24) * 4;
            *(float4*)&prs_s[t * 100 + c4] = *(const float4*)&pr[t * 96 + c4];
        }
        for (int i = tid; i < 1536; i += 256)
            sws[i] = sw[jf0 * 96 + i];
        __syncthreads();

        int rgrp = tid >> 4, cgrp = tid & 15;
        int c0 = cgrp * 6;
        const float* swr = &sws[rgrp * 96];
        float acc[6];
#pragma unroll
        for (int j = 0; j < 6; j++) acc[j] = 0.f;
#pragma unroll 4
        for (int t = 0; t < 96; t++) {
            float s = swr[t];
#pragma unroll
            for (int j = 0; j < 6; j++)
                acc[j] = fmaf(s, prs_s[t * 100 + c0 + j], acc[j]);
        }
        int jf = jf0 + rgrp;
#pragma unroll
        for (int j = 0; j < 6; j++)
            g_wbf[1][jf * 104 + c0 + j] = __float2bfloat16(acc[j]);
    } else {
        if (tid < 96) sws[tid] = prb[tid];
        __syncthreads();
        int rgrp = tid >> 4, cgrp = tid & 15;
        int c0 = cgrp * 6;
        for (int r = rgrp; r < 288; r += 16) {
            const float* swr = sw + r * 96;
            float pacc = 0.f;
#pragma unroll
            for (int t = 0; t < 6; t++)
                pacc = fmaf(swr[c0 + t], sws[c0 + t], pacc);
#pragma unroll
            for (int off = 1; off < 16; off <<= 1)
                pacc += __shfl_xor_sync(0xffffffffu, pacc, off);
            if (cgrp == 0) g_b1[r] = pacc + swb[r];
        }
    }
}

// ---------------------------------------------------------------------------
// One n-tile pair (tiles 2p, 2p+1): D[16 x 16] accumulated over K=96 with
// cached A fragments.
// ---------------------------------------------------------------------------
__device__ __forceinline__ void hmma_pair(const uint32_t af[6][4], uint32_t wAddr,
                                          int p, float acc[2][4])
{
#pragma unroll
    for (int t = 0; t < 2; t++)
#pragma unroll
        for (int r = 0; r < 4; r++) acc[t][r] = 0.f;
#pragma unroll
    for (int ks = 0; ks < 6; ks++) {
        uint32_t b0, b1, b2, b3;
        ldsm4(b0, b1, b2, b3, wAddr + p * 3328 + ks * 32);
        MMA(acc[0], af[ks], b0, b2);
        MMA(acc[1], af[ks], b1, b3);
    }
}

// stage one 96x104-bf16 weight image (19968B = 1248 x 16B) via cp.async
__device__ __forceinline__ void stage_w_async(uint32_t dst, const char* src, int tid)
{
    for (int f = tid; f < 1248; f += 256)
        CPA16(dst + f * 16, src + f * 16);
}

// ---------------------------------------------------------------------------
// Fused branch, mega-phase. Grid 256 x 256.
// Block = 64 position-groups x 2 frames.
// smem: tb 512 | qb 1152 | pb 384 | gt 2048 | gc 1024 | A 26624 | W x3 59904
// ---------------------------------------------------------------------------
__global__ void __launch_bounds__(256, 2)
fused_branch(const float* __restrict__ xin_ext,
             const float* __restrict__ qkv_b_ext,
             const float* __restrict__ pr_b,
             float* __restrict__ out_ext,
             int branch, int shift)
{
    extern __shared__ char smem[];
    int*   tb = (int*)smem;                 // 128 token bases
    float* qb = (float*)(smem + 512);       // 288 qkv biases
    float* pb = (float*)(smem + 1664);      // 96 proj biases
    float* gt = (float*)(smem + 2048);      // 128 x 4 per-token G
    float* gc = (float*)(smem + 4096);      // 64 x 4 per-group G
    char*  smA = smem + 5120;               // [128][104] bf16 (x / o tile)

    uint32_t sb   = smem_u32(smem);
    uint32_t smAu = sb + 5120;
    uint32_t smWu = sb + 31744;             // 3 x [96][104] bf16 slots

    int tid = threadIdx.x, w = tid >> 5, lane = tid & 31;
    int g = lane >> 2, tig = lane & 3;
    int l16 = lane & 15, lh = lane >> 4;
    int row0 = w * 16;

    const float* QB = branch ? g_b1 : qkv_b_ext;
    for (int i = tid; i < 288; i += 256) qb[i] = QB[i];
    if (branch && tid < 96) pb[tid] = pr_b[tid];

    if (tid < 128) {
        int pi = tid & 63;
        int gg = (blockIdx.x << 6) + pi;
        int b = gg >> 13, dw = (gg >> 10) & 7, p = gg & 1023;
        int d = (2 * dw + (tid >> 6) + shift) & 15;
        tb[tid] = ((b * 16 + d) * 1024 + p) * 96;
    }

    const char* WB = (const char*)g_wbf[branch];

    if (branch == 0) {
        stage_w_async(smWu,             WB + 96 * 208, tid);   // K -> slot0
        stage_w_async(smWu + 19968,     WB + 192 * 208, tid);  // V -> slot1
        stage_w_async(smWu + 2 * 19968, WB,             tid);  // Q -> slot2
        CPA_COMMIT();
        __syncthreads();   // tb ready
        for (int f4 = tid; f4 < 3072; f4 += 256) {
            int l = f4 / 24, q4 = f4 % 24;
            float4 v = *(const float4*)&xin_ext[tb[l] + q4 * 4];
            __nv_bfloat162 p0 = __floats2bfloat162_rn(v.x, v.y);
            __nv_bfloat162 p1 = __floats2bfloat162_rn(v.z, v.w);
            *(uint2*)(smA + l * 208 + q4 * 8) =
                make_uint2(*(uint32_t*)&p0, *(uint32_t*)&p1);
        }
    } else {
        __syncthreads();   // tb ready
        for (int f = tid; f < 1536; f += 256) {       // A tile via cp.async
            int l = f / 12, u = f % 12;
            CPA16(smAu + l * 208 + u * 16,
                  (const char*)g_mid + (size_t)tb[l] * 2 + u * 16);
        }
        stage_w_async(smWu,             WB + 96 * 208, tid);   // K
        stage_w_async(smWu + 19968,     WB + 192 * 208, tid);  // V
        stage_w_async(smWu + 2 * 19968, WB,             tid);  // Q
        CPA_COMMIT();
    }

    uint32_t aAddr = smAu + ((row0 + l16) * 104 + lh * 8) * 2;
    uint32_t wAddr = smWu + (l16 * 104 + lh * 8) * 2;

    CPA_WAIT(0);
    __syncthreads();        // A + K + V + Q visible

    // ---- cache A fragments (reused by K, V, Q) ----
    uint32_t af[6][4];
#pragma unroll
    for (int ks = 0; ks < 6; ks++)
        ldsm4(af[ks][0], af[ks][1], af[ks][2], af[ks][3], aAddr + ks * 32);

    // ---- mega loop: K, V, Q per pair; K/V fold into G; Q held in regs ----
    float G[8];
    float qacc[6][2][4];    // 48 persistent regs
#pragma unroll
    for (int i = 0; i < 8; i++) G[i] = 0.f;
#pragma unroll
    for (int p = 0; p < 6; p++) {
        float ka[2][4], va[2][4];
        hmma_pair(af, wAddr,             p, ka);
        hmma_pair(af, wAddr + 19968,     p, va);
        hmma_pair(af, wAddr + 2 * 19968, p, qacc[p]);
#pragma unroll
        for (int t = 0; t < 2; t++) {
            int j0 = (2 * p + t) * 8 + tig * 2;
            float kb0 = qb[96 + j0], kb1 = qb[96 + j0 + 1];
            float vb0 = qb[192 + j0], vb1 = qb[192 + j0 + 1];
            float k0 = ka[t][0] + kb0, k1 = ka[t][1] + kb1;
            float k2 = ka[t][2] + kb0, k3 = ka[t][3] + kb1;
            float v0 = va[t][0] + vb0, v1 = va[t][1] + vb1;
            float v2 = va[t][2] + vb0, v3 = va[t][3] + vb1;
            G[0] = fmaf(k0, v0, G[0]); G[1] = fmaf(k0, v1, G[1]);
            G[2] = fmaf(k1, v0, G[2]); G[3] = fmaf(k1, v1, G[3]);
            G[4] = fmaf(k2, v2, G[4]); G[5] = fmaf(k2, v3, G[5]);
            G[6] = fmaf(k3, v2, G[6]); G[7] = fmaf(k3, v3, G[7]);
        }
    }
    __syncthreads();        // all warps done reading weight slots

    // branch1: re-stage slot0 = proj weights (overlaps G reduction)
    if (branch) { stage_w_async(smWu, (const char*)g_wpbf, tid); CPA_COMMIT(); }

    // ---- reduce G across 4 lanes of each row, then across frame pair ----
#pragma unroll
    for (int off = 1; off <= 2; off <<= 1)
#pragma unroll
        for (int i = 0; i < 8; i++)
            G[i] += __shfl_xor_sync(0xffffffffu, G[i], off);
    if (tig == 0) {
        *(float4*)&gt[(row0 + g) * 4]     = make_float4(G[0], G[1], G[2], G[3]);
        *(float4*)&gt[(row0 + g + 8) * 4] = make_float4(G[4], G[5], G[6], G[7]);
    }
    __syncthreads();
    if (tid < 64) {
        float4 a = *(float4*)&gt[tid * 4];
        float4 b4 = *(float4*)&gt[(tid + 64) * 4];
        *(float4*)&gc[tid * 4] =
            make_float4(a.x + b4.x, a.y + b4.y, a.z + b4.z, a.w + b4.w);
    }
    CPA_WAIT(0);
    __syncthreads();        // gc (+ proj weights) visible

    float4 Glo = *(float4*)&gc[((row0 + g) & 63) * 4];
    float4 Ghi = *(float4*)&gc[((row0 + g + 8) & 63) * 4];

    // ---- apply G to held Q accumulators -> o bf16 into own smA rows ----
#pragma unroll
    for (int p = 0; p < 6; p++) {
#pragma unroll
        for (int t = 0; t < 2; t++) {
            int j0 = (2 * p + t) * 8 + tig * 2;
            float b0 = qb[j0], b1 = qb[j0 + 1];
            float q0 = qacc[p][t][0] + b0, q1 = qacc[p][t][1] + b1;
            float q2 = qacc[p][t][2] + b0, q3 = qacc[p][t][3] + b1;
            float o0 = q0 * Glo.x + q1 * Glo.z;
            float o1 = q0 * Glo.y + q1 * Glo.w;
            float o2 = q2 * Ghi.x + q3 * Ghi.z;
            float o3 = q2 * Ghi.y + q3 * Ghi.w;
            __nv_bfloat162 plo = __floats2bfloat162_rn(o0, o1);
            __nv_bfloat162 phi = __floats2bfloat162_rn(o2, o3);
            *(uint32_t*)(smA + (row0 + g) * 208 + j0 * 2)     = *(uint32_t*)&plo;
            *(uint32_t*)(smA + (row0 + g + 8) * 208 + j0 * 2) = *(uint32_t*)&phi;
        }
    }

    if (branch == 0) {
        // ---- o tile -> g_mid (coalesced uint4 rows) ----
        __syncthreads();
        for (int f = tid; f < 1536; f += 256) {
            int l = f / 12, u = f % 12;
            *(uint4*)((char*)g_mid + (size_t)tb[l] * 2 + u * 16) =
                *(const uint4*)(smA + l * 208 + u * 16);
        }
    } else {
        // ---- proj: o tile @ projs_w^T + pb -> out (warp-local A rows) ----
        __syncwarp();       // order own-warp STS -> LDSM
#pragma unroll
        for (int ks = 0; ks < 6; ks++)
            ldsm4(af[ks][0], af[ks][1], af[ks][2], af[ks][3], aAddr + ks * 32);
        int tbg = tb[row0 + g], tbh = tb[row0 + g + 8];
#pragma unroll
        for (int p = 0; p < 6; p++) {
            float pa[2][4];
            hmma_pair(af, wAddr, p, pa);    // slot0 = proj weights
#pragma unroll
            for (int t = 0; t < 2; t++) {
                int j0 = (2 * p + t) * 8 + tig * 2;
                float b0 = pb[j0], b1 = pb[j0 + 1];
                *(float2*)&out_ext[tbg + j0] =
                    make_float2(pa[t][0] + b0, pa[t][1] + b1);
                *(float2*)&out_ext[tbh + j0] =
                    make_float2(pa[t][2] + b0, pa[t][3] + b1);
            }
        }
    }
}

// ---------------------------------------------------------------------------
extern "C" void kernel_launch(void* const* d_in, const int* in_sizes, int n_in,
                              void* d_out, int out_size)
{
    const float* x       = (const float*)d_in[0];
    const float* lr_w    = (const float*)d_in[1];
    const float* lr_b    = (const float*)d_in[2];
    const float* proj_w  = (const float*)d_in[3];
    const float* proj_b  = (const float*)d_in[4];
    const float* sw_w    = (const float*)d_in[5];
    const float* sw_b    = (const float*)d_in[6];
    const float* projs_w = (const float*)d_in[7];
    const float* projs_b = (const float*)d_in[8];
    float* out = (float*)d_out;

    cudaFuncSetAttribute(fused_branch,
                         cudaFuncAttributeMaxDynamicSharedMemorySize, SMEM_BYTES);

    prep_all<<<163, 256>>>(lr_w, projs_w, proj_w, sw_w, sw_b, proj_b);
    // branch 0: pairs (2w, 2w+1), x -> o0 (g_mid bf16); proj folded forward
    fused_branch<<<256, 256, SMEM_BYTES>>>(x, lr_b, nullptr, nullptr, 0, 0);
    // branch 1: pairs ((2w+15)&15, 2w); qkv' on o0, projs -> out
    fused_branch<<<256, 256, SMEM_BYTES>>>(nullptr, nullptr, projs_b, out, 1, 15);
}